// round 5
// baseline (speedup 1.0000x reference)
#include <cuda_runtime.h>
#include <cuda_bf16.h>
#include <cstdint>
#include <cstddef>

// ---------------------------------------------------------------------------
// B=16, S=1024, DIM=768, H=12, HD=64
//   qkv(hi/lo bf16) = x @ W_attn + b_attn       (HMMA hi/lo x3)
//   attn            = causal MHA (HMMA hi/lo x3, ldmatrix.trans V, online softmax)
//   out             = attn @ W_proj + b_proj    (HMMA hi/lo x3, fp32 out)
// ---------------------------------------------------------------------------
#define BATCH 16
#define SEQ   1024
#define DIM   768
#define NH    12
#define HD    64
#define MROWS (BATCH * SEQ)
#define KTOT  768
#define N1    (3 * DIM)
#define N2    DIM

__device__ __nv_bfloat16  g_qkvh[MROWS * N1];
__device__ __nv_bfloat16  g_qkvl[MROWS * N1];
__device__ __nv_bfloat16  g_xh[MROWS * KTOT];
__device__ __nv_bfloat16  g_xl[MROWS * KTOT];
__device__ __nv_bfloat16  g_ah[MROWS * KTOT];
__device__ __nv_bfloat16  g_al[MROWS * KTOT];
__device__ __nv_bfloat16  g_wth[N1 * KTOT];
__device__ __nv_bfloat16  g_wtl[N1 * KTOT];

// ============================ PTX helpers ==================================
__device__ __forceinline__ uint32_t smem_u32(const void* p) {
    uint32_t a;
    asm("{ .reg .u64 t; cvta.to.shared.u64 t, %1; cvt.u32.u64 %0, t; }"
        : "=r"(a) : "l"(p));
    return a;
}

#define CP16(d, s) \
    asm volatile("cp.async.cg.shared.global [%0], [%1], 16;" :: "r"(d), "l"(s))
#define CP_COMMIT() asm volatile("cp.async.commit_group;" ::: "memory")
#define CP_WAIT(n)  asm volatile("cp.async.wait_group %0;" :: "n"(n) : "memory")

#define LDSM4(r0, r1, r2, r3, a) \
    asm volatile("ldmatrix.sync.aligned.m8n8.x4.shared.b16 {%0,%1,%2,%3}, [%4];" \
                 : "=r"(r0), "=r"(r1), "=r"(r2), "=r"(r3) : "r"(a))

#define LDSM4T(r0, r1, r2, r3, a) \
    asm volatile("ldmatrix.sync.aligned.m8n8.x4.trans.shared.b16 {%0,%1,%2,%3}, [%4];" \
                 : "=r"(r0), "=r"(r1), "=r"(r2), "=r"(r3) : "r"(a))

#define MMA_BF16(d, a0, a1, a2, a3, b0, b1) \
    asm volatile("mma.sync.aligned.m16n8k16.row.col.f32.bf16.bf16.f32 " \
                 "{%0,%1,%2,%3}, {%4,%5,%6,%7}, {%8,%9}, {%0,%1,%2,%3};" \
                 : "+f"((d)[0]), "+f"((d)[1]), "+f"((d)[2]), "+f"((d)[3]) \
                 : "r"(a0), "r"(a1), "r"(a2), "r"(a3), "r"(b0), "r"(b1))

__device__ __forceinline__ void pack_hl(float x, float y, uint32_t& h, uint32_t& l) {
    __nv_bfloat162 hb = __float22bfloat162_rn(make_float2(x, y));
    float2 hf = __bfloat1622float2(hb);
    __nv_bfloat162 lb = __float22bfloat162_rn(make_float2(x - hf.x, y - hf.y));
    h = *(uint32_t*)&hb;
    l = *(uint32_t*)&lb;
}

// ======================= conversion kernels ================================
__global__ __launch_bounds__(256) void split_fp32(
    const float* __restrict__ in, __nv_bfloat16* __restrict__ hi,
    __nv_bfloat16* __restrict__ lo, int n4)
{
    int i = blockIdx.x * 256 + threadIdx.x;
    if (i >= n4) return;
    float4 v = ((const float4*)in)[i];
    uint32_t h0, l0, h1, l1;
    pack_hl(v.x, v.y, h0, l0);
    pack_hl(v.z, v.w, h1, l1);
    ((uint32_t*)hi)[i * 2 + 0] = h0;
    ((uint32_t*)hi)[i * 2 + 1] = h1;
    ((uint32_t*)lo)[i * 2 + 0] = l0;
    ((uint32_t*)lo)[i * 2 + 1] = l1;
}

__global__ __launch_bounds__(256) void transpose_split(
    const float* __restrict__ W, __nv_bfloat16* __restrict__ Th,
    __nv_bfloat16* __restrict__ Tl, int K, int N)
{
    __shared__ float tile[32][33];
    int tx = threadIdx.x, ty = threadIdx.y;
    int nx = blockIdx.x * 32 + tx;
    int ky = blockIdx.y * 32 + ty;
    #pragma unroll
    for (int j = 0; j < 32; j += 8)
        tile[ty + j][tx] = W[(size_t)(ky + j) * N + nx];
    __syncthreads();
    int kx = blockIdx.y * 32 + tx;
    int ny = blockIdx.x * 32 + ty;
    #pragma unroll
    for (int j = 0; j < 32; j += 8) {
        float v = tile[tx][ty + j];
        __nv_bfloat16 h = __float2bfloat16(v);
        __nv_bfloat16 l = __float2bfloat16(v - __bfloat162float(h));
        Th[(size_t)(ny + j) * K + kx] = h;
        Tl[(size_t)(ny + j) * K + kx] = l;
    }
}

// ===================== HMMA GEMM (bf16 hi/lo x3) ===========================
// C[M,Ntot] = (Ah+Al)[M,768] @ (Bh+Bl)[Ntot,768]^T + bias
// 128x192 tile, BK=64, 2 stages, 384 threads (12 warps, 32x64 each).
#define GTHREADS 384
#define NIT     12
#define T_AH    0
#define T_AL    16384
#define T_BH    32768
#define T_BL    57344
#define STG     81920
#define GEMM_SMEM (2 * STG)       // 163840

__device__ __forceinline__ void stage_load(
    uint32_t sstage,
    const __nv_bfloat16* Ah, const __nv_bfloat16* Al,
    const __nv_bfloat16* Bh, const __nv_bfloat16* Bl,
    int mtile, int ntile, int kiter, int tid)
{
    // A tiles: 2 x 128 rows x 8 cp16
    for (int idx = tid; idx < 2048; idx += GTHREADS) {
        int hl = idx >> 10, rem = idx & 1023;
        int r = rem >> 3, c = rem & 7;
        const __nv_bfloat16* src = (hl ? Al : Ah)
            + (size_t)(mtile * 128 + r) * KTOT + kiter * 64 + c * 8;
        CP16(sstage + (hl ? T_AL : T_AH) + r * 128 + ((c ^ (r & 7)) << 4), src);
    }
    // B tiles: 2 x 192 rows x 8 cp16
    for (int idx = tid; idx < 3072; idx += GTHREADS) {
        int hl = idx >= 1536 ? 1 : 0;
        int rem = idx - hl * 1536;
        int r = rem >> 3, c = rem & 7;
        const __nv_bfloat16* src = (hl ? Bl : Bh)
            + (size_t)(ntile * 192 + r) * KTOT + kiter * 64 + c * 8;
        CP16(sstage + (hl ? T_BL : T_BH) + r * 128 + ((c ^ (r & 7)) << 4), src);
    }
}

template<int OUTHL>
__global__ __launch_bounds__(GTHREADS) void gemm_mma(
    const __nv_bfloat16* __restrict__ Ah, const __nv_bfloat16* __restrict__ Al,
    const __nv_bfloat16* __restrict__ Bh, const __nv_bfloat16* __restrict__ Bl,
    const float* __restrict__ bias, float* __restrict__ Cf,
    __nv_bfloat16* __restrict__ Ch, __nv_bfloat16* __restrict__ Cl, int Ntot)
{
    extern __shared__ char smem[];
    const uint32_t sb = smem_u32(smem);
    const int tid = threadIdx.x, lane = tid & 31, wid = tid >> 5;
    const int mtile = blockIdx.y, ntile = blockIdx.x;
    const int wm = (wid & 3) * 32;        // 4 m-groups
    const int wn = (wid >> 2) * 64;       // 3 n-groups

    const int rowA  = wm + (lane & 15);
    const int xorA  = rowA & 7;
    const int clA   = lane >> 4;
    const int rowB  = wn + ((lane >> 4) << 3) + (lane & 7);
    const int xorB  = rowB & 7;
    const int clB   = (lane >> 3) & 1;

    float acc[2][8][4];
    #pragma unroll
    for (int mf = 0; mf < 2; mf++)
        #pragma unroll
        for (int nf = 0; nf < 8; nf++)
            #pragma unroll
            for (int q = 0; q < 4; q++) acc[mf][nf][q] = 0.f;

    stage_load(sb + 0 * STG, Ah, Al, Bh, Bl, mtile, ntile, 0, tid); CP_COMMIT();
    stage_load(sb + 1 * STG, Ah, Al, Bh, Bl, mtile, ntile, 1, tid); CP_COMMIT();

    for (int i = 0; i < NIT; i++) {
        if (i + 1 < NIT) { CP_WAIT(1); } else { CP_WAIT(0); }
        __syncthreads();

        const uint32_t st = sb + (i & 1) * STG;
        #pragma unroll
        for (int ks = 0; ks < 4; ks++) {
            uint32_t ah[2][4], al[2][4], bh[8][2], bl[8][2];
            #pragma unroll
            for (int mf = 0; mf < 2; mf++) {
                uint32_t off = (uint32_t)((rowA + mf * 16) * 128 +
                               ((((ks << 1) + clA) ^ xorA) << 4));
                LDSM4(ah[mf][0], ah[mf][1], ah[mf][2], ah[mf][3], st + T_AH + off);
                LDSM4(al[mf][0], al[mf][1], al[mf][2], al[mf][3], st + T_AL + off);
            }
            #pragma unroll
            for (int nf2 = 0; nf2 < 4; nf2++) {
                uint32_t off = (uint32_t)((rowB + nf2 * 16) * 128 +
                               ((((ks << 1) + clB) ^ xorB) << 4));
                LDSM4(bh[nf2 * 2][0], bh[nf2 * 2][1],
                      bh[nf2 * 2 + 1][0], bh[nf2 * 2 + 1][1], st + T_BH + off);
                LDSM4(bl[nf2 * 2][0], bl[nf2 * 2][1],
                      bl[nf2 * 2 + 1][0], bl[nf2 * 2 + 1][1], st + T_BL + off);
            }
            #pragma unroll
            for (int mf = 0; mf < 2; mf++)
                #pragma unroll
                for (int nf = 0; nf < 8; nf++) {
                    MMA_BF16(acc[mf][nf], ah[mf][0], ah[mf][1], ah[mf][2], ah[mf][3],
                             bh[nf][0], bh[nf][1]);
                    MMA_BF16(acc[mf][nf], ah[mf][0], ah[mf][1], ah[mf][2], ah[mf][3],
                             bl[nf][0], bl[nf][1]);
                    MMA_BF16(acc[mf][nf], al[mf][0], al[mf][1], al[mf][2], al[mf][3],
                             bh[nf][0], bh[nf][1]);
                }
        }
        __syncthreads();
        if (i + 2 < NIT) {
            stage_load(sb + (i & 1) * STG, Ah, Al, Bh, Bl, mtile, ntile, i + 2, tid);
            CP_COMMIT();
        }
    }

    #pragma unroll
    for (int mf = 0; mf < 2; mf++) {
        #pragma unroll
        for (int nf = 0; nf < 8; nf++) {
            const int col = ntile * 192 + wn + nf * 8 + (lane & 3) * 2;
            const int row0 = mtile * 128 + wm + mf * 16 + (lane >> 2);
            const float b0 = bias[col], b1 = bias[col + 1];
            float v0 = acc[mf][nf][0] + b0, v1 = acc[mf][nf][1] + b1;
            float v2 = acc[mf][nf][2] + b0, v3 = acc[mf][nf][3] + b1;
            if (OUTHL) {
                uint32_t h0, l0, h1, l1;
                pack_hl(v0, v1, h0, l0);
                pack_hl(v2, v3, h1, l1);
                *(uint32_t*)&Ch[(size_t)row0 * Ntot + col] = h0;
                *(uint32_t*)&Cl[(size_t)row0 * Ntot + col] = l0;
                *(uint32_t*)&Ch[(size_t)(row0 + 8) * Ntot + col] = h1;
                *(uint32_t*)&Cl[(size_t)(row0 + 8) * Ntot + col] = l1;
            } else {
                *(float2*)&Cf[(size_t)row0 * Ntot + col] = make_float2(v0, v1);
                *(float2*)&Cf[(size_t)(row0 + 8) * Ntot + col] = make_float2(v2, v3);
            }
        }
    }
}

// ===================== tensor-core causal flash attention ==================
// CTA: 128 q-rows x 1 head. 8 warps x 16 rows. Double-buffered K/V stages.
// V stored row-major [kv][d] like K; PV B-frags via ldmatrix.trans.
#define A_KH   0
#define A_KL   16384
#define A_VH   32768
#define A_VL   49152
#define A_BUF  65536
#define ATT_SMEM 131072
#define C1 0.18033688011112042f   // 0.125 * log2(e)

__device__ __forceinline__ void attn_load_kv(
    uint32_t bufbase,
    const __nv_bfloat16* qkvh, const __nv_bfloat16* qkvl,
    int b, int h, int jt, int tid)
{
    // K tile: 128 rows x 64 bf16, hi/lo
    #pragma unroll
    for (int j = 0; j < 8; j++) {
        int idx = tid + j * 256;
        int hl = idx >> 10, r = (idx >> 3) & 127, c = idx & 7;
        const __nv_bfloat16* src = (hl ? qkvl : qkvh)
            + (size_t)(b * SEQ + jt * 128 + r) * N1 + DIM + h * HD + c * 8;
        CP16(bufbase + hl * 16384 + r * 128 + ((c ^ (r & 7)) << 4), src);
    }
    // V tile: 128 rows x 64 bf16, hi/lo (row-major, same pattern)
    #pragma unroll
    for (int j = 0; j < 8; j++) {
        int idx = tid + j * 256;
        int hl = idx >> 10, r = (idx >> 3) & 127, c = idx & 7;
        const __nv_bfloat16* src = (hl ? qkvl : qkvh)
            + (size_t)(b * SEQ + jt * 128 + r) * N1 + 2 * DIM + h * HD + c * 8;
        CP16(bufbase + A_VH + hl * 16384 + r * 128 + ((c ^ (r & 7)) << 4), src);
    }
}

__global__ __launch_bounds__(256, 1) void attn_mma(
    const __nv_bfloat16* __restrict__ qkvh, const __nv_bfloat16* __restrict__ qkvl,
    __nv_bfloat16* __restrict__ oh, __nv_bfloat16* __restrict__ ol)
{
    extern __shared__ char smem[];
    const uint32_t sb = smem_u32(smem);
    const int tid = threadIdx.x, lane = tid & 31, w = tid >> 5;
    const int qt = blockIdx.x, h = blockIdx.y, b = blockIdx.z;
    const int nt = qt + 1;

    // ---- stage Q tile into buf0 K region, then to fragments ----
    #pragma unroll
    for (int j = 0; j < 8; j++) {
        int idx = tid + j * 256;
        int hl = idx >> 10, r = (idx >> 3) & 127, c = idx & 7;
        const __nv_bfloat16* src = (hl ? qkvl : qkvh)
            + (size_t)(b * SEQ + qt * 128 + r) * N1 + h * HD + c * 8;
        CP16(sb + hl * 16384 + r * 128 + ((c ^ (r & 7)) << 4), src);
    }
    CP_COMMIT(); CP_WAIT(0);
    __syncthreads();

    const int rowA = w * 16 + (lane & 15);
    const int clA = lane >> 4, xorA = rowA & 7;
    uint32_t qh[4][4], ql[4][4];
    #pragma unroll
    for (int ks = 0; ks < 4; ks++) {
        uint32_t off = (uint32_t)(rowA * 128 + ((((ks << 1) + clA) ^ xorA) << 4));
        LDSM4(qh[ks][0], qh[ks][1], qh[ks][2], qh[ks][3], sb + off);
        LDSM4(ql[ks][0], ql[ks][1], ql[ks][2], ql[ks][3], sb + 16384 + off);
    }
    __syncthreads();

    attn_load_kv(sb, qkvh, qkvl, b, h, 0, tid);
    CP_COMMIT();

    float m2[2] = {-1e30f, -1e30f}, lsum[2] = {0.f, 0.f};
    float o[8][4];
    #pragma unroll
    for (int nf = 0; nf < 8; nf++)
        #pragma unroll
        for (int q = 0; q < 4; q++) o[nf][q] = 0.f;

    // K ldsm (non-trans) lane mapping
    const int rowB = ((lane >> 4) << 3) + (lane & 7);
    const int clB = (lane >> 3) & 1, xorB = lane & 7;
    // V ldsm.trans lane mapping: kr within 16-row chunk, dc = 16B col unit
    const int vkr = (lane & 7) + ((lane >> 3) & 1) * 8;
    const int vdc = lane >> 4;

    for (int jt = 0; jt < nt; jt++) {
        CP_WAIT(0);
        __syncthreads();
        if (jt + 1 < nt) {
            attn_load_kv(sb + ((jt + 1) & 1) * A_BUF, qkvh, qkvl, b, h, jt + 1, tid);
            CP_COMMIT();
        }
        const uint32_t kb = sb + (jt & 1) * A_BUF;

        // ---- scores S = Q K^T ----
        float s[16][4];
        #pragma unroll
        for (int nf = 0; nf < 16; nf++)
            #pragma unroll
            for (int q = 0; q < 4; q++) s[nf][q] = 0.f;

        #pragma unroll
        for (int ks = 0; ks < 4; ks++) {
            #pragma unroll
            for (int nf2 = 0; nf2 < 8; nf2++) {
                uint32_t off = (uint32_t)((rowB + nf2 * 16) * 128 +
                               ((((ks << 1) + clB) ^ xorB) << 4));
                uint32_t kh0, kh1, kh2, kh3, kl0, kl1, kl2, kl3;
                LDSM4(kh0, kh1, kh2, kh3, kb + A_KH + off);
                LDSM4(kl0, kl1, kl2, kl3, kb + A_KL + off);
                MMA_BF16(s[nf2 * 2], qh[ks][0], qh[ks][1], qh[ks][2], qh[ks][3], kh0, kh1);
                MMA_BF16(s[nf2 * 2], qh[ks][0], qh[ks][1], qh[ks][2], qh[ks][3], kl0, kl1);
                MMA_BF16(s[nf2 * 2], ql[ks][0], ql[ks][1], ql[ks][2], ql[ks][3], kh0, kh1);
                MMA_BF16(s[nf2 * 2 + 1], qh[ks][0], qh[ks][1], qh[ks][2], qh[ks][3], kh2, kh3);
                MMA_BF16(s[nf2 * 2 + 1], qh[ks][0], qh[ks][1], qh[ks][2], qh[ks][3], kl2, kl3);
                MMA_BF16(s[nf2 * 2 + 1], ql[ks][0], ql[ks][1], ql[ks][2], ql[ks][3], kh2, kh3);
            }
        }

        // ---- causal mask (diagonal tile only) ----
        if (jt == qt) {
            const int r0l = w * 16 + (lane >> 2);
            #pragma unroll
            for (int nf = 0; nf < 16; nf++) {
                const int c0l = nf * 8 + (lane & 3) * 2;
                if (c0l     > r0l)     s[nf][0] = -3e38f;
                if (c0l + 1 > r0l)     s[nf][1] = -3e38f;
                if (c0l     > r0l + 8) s[nf][2] = -3e38f;
                if (c0l + 1 > r0l + 8) s[nf][3] = -3e38f;
            }
        }

        // ---- online softmax (base-2) ----
        float mx0 = -3e38f, mx1 = -3e38f;
        #pragma unroll
        for (int nf = 0; nf < 16; nf++) {
            mx0 = fmaxf(mx0, fmaxf(s[nf][0], s[nf][1]));
            mx1 = fmaxf(mx1, fmaxf(s[nf][2], s[nf][3]));
        }
        mx0 = fmaxf(mx0, __shfl_xor_sync(0xffffffffu, mx0, 1));
        mx0 = fmaxf(mx0, __shfl_xor_sync(0xffffffffu, mx0, 2));
        mx1 = fmaxf(mx1, __shfl_xor_sync(0xffffffffu, mx1, 1));
        mx1 = fmaxf(mx1, __shfl_xor_sync(0xffffffffu, mx1, 2));
        const float m2n0 = fmaxf(m2[0], mx0 * C1);
        const float m2n1 = fmaxf(m2[1], mx1 * C1);
        const float corr0 = exp2f(m2[0] - m2n0);
        const float corr1 = exp2f(m2[1] - m2n1);
        m2[0] = m2n0; m2[1] = m2n1;

        float rs0 = 0.f, rs1 = 0.f;
        #pragma unroll
        for (int nf = 0; nf < 16; nf++) {
            s[nf][0] = exp2f(fmaf(s[nf][0], C1, -m2n0)); rs0 += s[nf][0];
            s[nf][1] = exp2f(fmaf(s[nf][1], C1, -m2n0)); rs0 += s[nf][1];
            s[nf][2] = exp2f(fmaf(s[nf][2], C1, -m2n1)); rs1 += s[nf][2];
            s[nf][3] = exp2f(fmaf(s[nf][3], C1, -m2n1)); rs1 += s[nf][3];
        }
        rs0 += __shfl_xor_sync(0xffffffffu, rs0, 1);
        rs0 += __shfl_xor_sync(0xffffffffu, rs0, 2);
        rs1 += __shfl_xor_sync(0xffffffffu, rs1, 1);
        rs1 += __shfl_xor_sync(0xffffffffu, rs1, 2);
        lsum[0] = lsum[0] * corr0 + rs0;
        lsum[1] = lsum[1] * corr1 + rs1;
        #pragma unroll
        for (int nf = 0; nf < 8; nf++) {
            o[nf][0] *= corr0; o[nf][1] *= corr0;
            o[nf][2] *= corr1; o[nf][3] *= corr1;
        }

        // ---- O += P V  (P frags in-register; V via ldmatrix.trans) ----
        #pragma unroll
        for (int kc = 0; kc < 8; kc++) {
            uint32_t pa0, pa1, pa2, pa3, pb0, pb1, pb2, pb3;
            pack_hl(s[2 * kc][0],     s[2 * kc][1],     pa0, pb0);
            pack_hl(s[2 * kc][2],     s[2 * kc][3],     pa1, pb1);
            pack_hl(s[2 * kc + 1][0], s[2 * kc + 1][1], pa2, pb2);
            pack_hl(s[2 * kc + 1][2], s[2 * kc + 1][3], pa3, pb3);
            const int kr = kc * 16 + vkr;
            #pragma unroll
            for (int nf2 = 0; nf2 < 4; nf2++) {
                uint32_t off = (uint32_t)(kr * 128 +
                               (((nf2 * 2 + vdc) ^ (kr & 7)) << 4));
                uint32_t vh0, vh1, vh2, vh3, vl0, vl1, vl2, vl3;
                LDSM4T(vh0, vh1, vh2, vh3, kb + A_VH + off);
                LDSM4T(vl0, vl1, vl2, vl3, kb + A_VL + off);
                MMA_BF16(o[nf2 * 2], pa0, pa1, pa2, pa3, vh0, vh1);
                MMA_BF16(o[nf2 * 2], pa0, pa1, pa2, pa3, vl0, vl1);
                MMA_BF16(o[nf2 * 2], pb0, pb1, pb2, pb3, vh0, vh1);
                MMA_BF16(o[nf2 * 2 + 1], pa0, pa1, pa2, pa3, vh2, vh3);
                MMA_BF16(o[nf2 * 2 + 1], pa0, pa1, pa2, pa3, vl2, vl3);
                MMA_BF16(o[nf2 * 2 + 1], pb0, pb1, pb2, pb3, vh2, vh3);
            }
        }
    }

    // ---- normalize + write bf16 hi/lo ----
    const float inv0 = 1.f / lsum[0], inv1 = 1.f / lsum[1];
    const size_t gr = (size_t)(b * SEQ + qt * 128 + w * 16 + (lane >> 2));
    const int colb = h * HD + (lane & 3) * 2;
    #pragma unroll
    for (int nf = 0; nf < 8; nf++) {
        const int col = colb + nf * 8;
        uint32_t h0, l0, h1, l1;
        pack_hl(o[nf][0] * inv0, o[nf][1] * inv0, h0, l0);
        pack_hl(o[nf][2] * inv1, o[nf][3] * inv1, h1, l1);
        *(uint32_t*)&oh[gr * DIM + col] = h0;
        *(uint32_t*)&ol[gr * DIM + col] = l0;
        *(uint32_t*)&oh[(gr + 8) * DIM + col] = h1;
        *(uint32_t*)&ol[(gr + 8) * DIM + col] = l1;
    }
}

// =============================== launch ====================================
extern "C" void kernel_launch(void* const* d_in, const int* in_sizes, int n_in,
                              void* d_out, int out_size)
{
    const float* x      = (const float*)d_in[0];
    const float* W_attn = (const float*)d_in[1];
    const float* b_attn = (const float*)d_in[2];
    const float* W_proj = (const float*)d_in[3];
    const float* b_proj = (const float*)d_in[4];
    float* out = (float*)d_out;

    __nv_bfloat16 *qkvh, *qkvl, *xh, *xl, *ahp, *alp, *wth, *wtl;
    cudaGetSymbolAddress((void**)&qkvh, g_qkvh);
    cudaGetSymbolAddress((void**)&qkvl, g_qkvl);
    cudaGetSymbolAddress((void**)&xh,  g_xh);
    cudaGetSymbolAddress((void**)&xl,  g_xl);
    cudaGetSymbolAddress((void**)&ahp, g_ah);
    cudaGetSymbolAddress((void**)&alp, g_al);
    cudaGetSymbolAddress((void**)&wth, g_wth);
    cudaGetSymbolAddress((void**)&wtl, g_wtl);

    static int attrs_set = 0;
    if (!attrs_set) {
        cudaFuncSetAttribute(gemm_mma<0>, cudaFuncAttributeMaxDynamicSharedMemorySize, GEMM_SMEM);
        cudaFuncSetAttribute(gemm_mma<1>, cudaFuncAttributeMaxDynamicSharedMemorySize, GEMM_SMEM);
        cudaFuncSetAttribute(attn_mma, cudaFuncAttributeMaxDynamicSharedMemorySize, ATT_SMEM);
        attrs_set = 1;
    }

    // 1) x -> bf16 hi/lo
    {
        int n4 = MROWS * KTOT / 4;
        split_fp32<<<(n4 + 255) / 256, 256>>>(x, xh, xl, n4);
    }
    // 2) W_attn -> transposed hi/lo
    transpose_split<<<dim3(N1 / 32, KTOT / 32), dim3(32, 8)>>>(W_attn, wth, wtl, KTOT, N1);
    // 3) qkv GEMM -> bf16 hi/lo
    gemm_mma<1><<<dim3(N1 / 192, MROWS / 128), GTHREADS, GEMM_SMEM>>>(
        xh, xl, wth, wtl, b_attn, nullptr, qkvh, qkvl, N1);
    // 4) attention (tensor cores, V via ldmatrix.trans)
    attn_mma<<<dim3(SEQ / 128, NH, BATCH), 256, ATT_SMEM>>>(
        qkvh, qkvl, ahp, alp);
    // 5) W_proj -> transposed hi/lo
    transpose_split<<<dim3(N2 / 32, KTOT / 32), dim3(32, 8)>>>(W_proj, wth, wtl, KTOT, N2);
    // 6) out GEMM (fp32 out)
    gemm_mma<0><<<dim3(N2 / 192, MROWS / 128), GTHREADS, GEMM_SMEM>>>(
        ahp, alp, wth, wtl, b_proj, out, nullptr, nullptr, N2);
}

// round 6
// speedup vs baseline: 1.0778x; 1.0778x over previous
#include <cuda_runtime.h>
#include <cuda_bf16.h>
#include <cstdint>
#include <cstddef>

// ---------------------------------------------------------------------------
// B=16, S=1024, DIM=768, H=12, HD=64
//   qkv(hi/lo bf16) = x @ W_attn + b_attn       (HMMA hi/lo x3)
//   attn            = causal MHA (HMMA hi/lo x3, ldmatrix.trans V, online softmax)
//   out             = attn @ W_proj + b_proj    (HMMA hi/lo x3, fp32 out)
// ---------------------------------------------------------------------------
#define BATCH 16
#define SEQ   1024
#define DIM   768
#define NH    12
#define HD    64
#define MROWS (BATCH * SEQ)
#define KTOT  768
#define N1    (3 * DIM)
#define N2    DIM

__device__ __nv_bfloat16  g_qkvh[MROWS * N1];
__device__ __nv_bfloat16  g_qkvl[MROWS * N1];
__device__ __nv_bfloat16  g_xh[MROWS * KTOT];
__device__ __nv_bfloat16  g_xl[MROWS * KTOT];
__device__ __nv_bfloat16  g_ah[MROWS * KTOT];
__device__ __nv_bfloat16  g_al[MROWS * KTOT];
__device__ __nv_bfloat16  g_wth[N1 * KTOT];
__device__ __nv_bfloat16  g_wtl[N1 * KTOT];

// ============================ PTX helpers ==================================
__device__ __forceinline__ uint32_t smem_u32(const void* p) {
    uint32_t a;
    asm("{ .reg .u64 t; cvta.to.shared.u64 t, %1; cvt.u32.u64 %0, t; }"
        : "=r"(a) : "l"(p));
    return a;
}

#define CP16(d, s) \
    asm volatile("cp.async.cg.shared.global [%0], [%1], 16;" :: "r"(d), "l"(s))
#define CP_COMMIT() asm volatile("cp.async.commit_group;" ::: "memory")
#define CP_WAIT(n)  asm volatile("cp.async.wait_group %0;" :: "n"(n) : "memory")

#define LDSM4(r0, r1, r2, r3, a) \
    asm volatile("ldmatrix.sync.aligned.m8n8.x4.shared.b16 {%0,%1,%2,%3}, [%4];" \
                 : "=r"(r0), "=r"(r1), "=r"(r2), "=r"(r3) : "r"(a))

#define LDSM4T(r0, r1, r2, r3, a) \
    asm volatile("ldmatrix.sync.aligned.m8n8.x4.trans.shared.b16 {%0,%1,%2,%3}, [%4];" \
                 : "=r"(r0), "=r"(r1), "=r"(r2), "=r"(r3) : "r"(a))

#define MMA_BF16(d, a0, a1, a2, a3, b0, b1) \
    asm volatile("mma.sync.aligned.m16n8k16.row.col.f32.bf16.bf16.f32 " \
                 "{%0,%1,%2,%3}, {%4,%5,%6,%7}, {%8,%9}, {%0,%1,%2,%3};" \
                 : "+f"((d)[0]), "+f"((d)[1]), "+f"((d)[2]), "+f"((d)[3]) \
                 : "r"(a0), "r"(a1), "r"(a2), "r"(a3), "r"(b0), "r"(b1))

__device__ __forceinline__ void pack_hl(float x, float y, uint32_t& h, uint32_t& l) {
    __nv_bfloat162 hb = __float22bfloat162_rn(make_float2(x, y));
    float2 hf = __bfloat1622float2(hb);
    __nv_bfloat162 lb = __float22bfloat162_rn(make_float2(x - hf.x, y - hf.y));
    h = *(uint32_t*)&hb;
    l = *(uint32_t*)&lb;
}

// ======================= conversion kernels ================================
__global__ __launch_bounds__(256) void split_fp32(
    const float* __restrict__ in, __nv_bfloat16* __restrict__ hi,
    __nv_bfloat16* __restrict__ lo, int n4)
{
    int i = blockIdx.x * 256 + threadIdx.x;
    if (i >= n4) return;
    float4 v = ((const float4*)in)[i];
    uint32_t h0, l0, h1, l1;
    pack_hl(v.x, v.y, h0, l0);
    pack_hl(v.z, v.w, h1, l1);
    ((uint32_t*)hi)[i * 2 + 0] = h0;
    ((uint32_t*)hi)[i * 2 + 1] = h1;
    ((uint32_t*)lo)[i * 2 + 0] = l0;
    ((uint32_t*)lo)[i * 2 + 1] = l1;
}

__global__ __launch_bounds__(256) void transpose_split(
    const float* __restrict__ W, __nv_bfloat16* __restrict__ Th,
    __nv_bfloat16* __restrict__ Tl, int K, int N)
{
    __shared__ float tile[32][33];
    int tx = threadIdx.x, ty = threadIdx.y;
    int nx = blockIdx.x * 32 + tx;
    int ky = blockIdx.y * 32 + ty;
    #pragma unroll
    for (int j = 0; j < 32; j += 8)
        tile[ty + j][tx] = W[(size_t)(ky + j) * N + nx];
    __syncthreads();
    int kx = blockIdx.y * 32 + tx;
    int ny = blockIdx.x * 32 + ty;
    #pragma unroll
    for (int j = 0; j < 32; j += 8) {
        float v = tile[tx][ty + j];
        __nv_bfloat16 h = __float2bfloat16(v);
        __nv_bfloat16 l = __float2bfloat16(v - __bfloat162float(h));
        Th[(size_t)(ny + j) * K + kx] = h;
        Tl[(size_t)(ny + j) * K + kx] = l;
    }
}

// ===================== HMMA GEMM (bf16 hi/lo x3) ===========================
// R4-proven config: 128x128 tile, BK=64, 3 stages, 256 threads (8 warps 32x64).
#define BK      64
#define NSTG    3
#define NIT     12
#define T_AH    0
#define T_AL    16384
#define T_BH    32768
#define T_BL    49152
#define STG     65536
#define GEMM_SMEM (NSTG * STG)

__device__ __forceinline__ void stage_load(
    uint32_t sstage,
    const __nv_bfloat16* Ah, const __nv_bfloat16* Al,
    const __nv_bfloat16* Bh, const __nv_bfloat16* Bl,
    int mtile, int ntile, int kiter, int tid)
{
    #pragma unroll
    for (int j = 0; j < 4; j++) {
        int cidx = tid + j * 256;
        int r = cidx >> 3, c = cidx & 7;
        uint32_t so = (uint32_t)(r * 128 + (((c) ^ (r & 7)) << 4));
        size_t gA = (size_t)(mtile * 128 + r) * KTOT + kiter * BK + c * 8;
        size_t gB = (size_t)(ntile * 128 + r) * KTOT + kiter * BK + c * 8;
        CP16(sstage + T_AH + so, (const char*)(Ah + gA));
        CP16(sstage + T_AL + so, (const char*)(Al + gA));
        CP16(sstage + T_BH + so, (const char*)(Bh + gB));
        CP16(sstage + T_BL + so, (const char*)(Bl + gB));
    }
}

template<int OUTHL>
__global__ __launch_bounds__(256) void gemm_mma(
    const __nv_bfloat16* __restrict__ Ah, const __nv_bfloat16* __restrict__ Al,
    const __nv_bfloat16* __restrict__ Bh, const __nv_bfloat16* __restrict__ Bl,
    const float* __restrict__ bias, float* __restrict__ Cf,
    __nv_bfloat16* __restrict__ Ch, __nv_bfloat16* __restrict__ Cl, int Ntot)
{
    extern __shared__ char smem[];
    const uint32_t sb = smem_u32(smem);
    const int tid = threadIdx.x, lane = tid & 31, wid = tid >> 5;
    const int mtile = blockIdx.y, ntile = blockIdx.x;
    const int wm = (wid & 3) * 32;
    const int wn = (wid >> 2) * 64;

    const int rowA  = wm + (lane & 15);
    const int xorA  = rowA & 7;
    const int clA   = lane >> 4;
    const int rowB  = wn + ((lane >> 4) << 3) + (lane & 7);
    const int xorB  = rowB & 7;
    const int clB   = (lane >> 3) & 1;

    float acc[2][8][4];
    #pragma unroll
    for (int mf = 0; mf < 2; mf++)
        #pragma unroll
        for (int nf = 0; nf < 8; nf++)
            #pragma unroll
            for (int q = 0; q < 4; q++) acc[mf][nf][q] = 0.f;

    stage_load(sb + 0 * STG, Ah, Al, Bh, Bl, mtile, ntile, 0, tid); CP_COMMIT();
    stage_load(sb + 1 * STG, Ah, Al, Bh, Bl, mtile, ntile, 1, tid); CP_COMMIT();

    for (int i = 0; i < NIT; i++) {
        if (i + 2 < NIT) {
            stage_load(sb + ((i + 2) % NSTG) * STG, Ah, Al, Bh, Bl,
                       mtile, ntile, i + 2, tid);
            CP_COMMIT();
            CP_WAIT(2);
        } else if (i + 1 < NIT) {
            CP_WAIT(1);
        } else {
            CP_WAIT(0);
        }
        __syncthreads();

        const uint32_t st = sb + (i % NSTG) * STG;
        #pragma unroll
        for (int ks = 0; ks < 4; ks++) {
            uint32_t ah[2][4], al[2][4], bh[8][2], bl[8][2];
            #pragma unroll
            for (int mf = 0; mf < 2; mf++) {
                uint32_t off = (uint32_t)((rowA + mf * 16) * 128 +
                               ((((ks << 1) + clA) ^ xorA) << 4));
                LDSM4(ah[mf][0], ah[mf][1], ah[mf][2], ah[mf][3], st + T_AH + off);
                LDSM4(al[mf][0], al[mf][1], al[mf][2], al[mf][3], st + T_AL + off);
            }
            #pragma unroll
            for (int nf2 = 0; nf2 < 4; nf2++) {
                uint32_t off = (uint32_t)((rowB + nf2 * 16) * 128 +
                               ((((ks << 1) + clB) ^ xorB) << 4));
                LDSM4(bh[nf2 * 2][0], bh[nf2 * 2][1],
                      bh[nf2 * 2 + 1][0], bh[nf2 * 2 + 1][1], st + T_BH + off);
                LDSM4(bl[nf2 * 2][0], bl[nf2 * 2][1],
                      bl[nf2 * 2 + 1][0], bl[nf2 * 2 + 1][1], st + T_BL + off);
            }
            #pragma unroll
            for (int mf = 0; mf < 2; mf++)
                #pragma unroll
                for (int nf = 0; nf < 8; nf++) {
                    MMA_BF16(acc[mf][nf], ah[mf][0], ah[mf][1], ah[mf][2], ah[mf][3],
                             bh[nf][0], bh[nf][1]);
                    MMA_BF16(acc[mf][nf], ah[mf][0], ah[mf][1], ah[mf][2], ah[mf][3],
                             bl[nf][0], bl[nf][1]);
                    MMA_BF16(acc[mf][nf], al[mf][0], al[mf][1], al[mf][2], al[mf][3],
                             bh[nf][0], bh[nf][1]);
                }
        }
        __syncthreads();
    }

    #pragma unroll
    for (int mf = 0; mf < 2; mf++) {
        #pragma unroll
        for (int nf = 0; nf < 8; nf++) {
            const int col = ntile * 128 + wn + nf * 8 + (lane & 3) * 2;
            const int row0 = mtile * 128 + wm + mf * 16 + (lane >> 2);
            const float b0 = bias[col], b1 = bias[col + 1];
            float v0 = acc[mf][nf][0] + b0, v1 = acc[mf][nf][1] + b1;
            float v2 = acc[mf][nf][2] + b0, v3 = acc[mf][nf][3] + b1;
            if (OUTHL) {
                uint32_t h0, l0, h1, l1;
                pack_hl(v0, v1, h0, l0);
                pack_hl(v2, v3, h1, l1);
                *(uint32_t*)&Ch[(size_t)row0 * Ntot + col] = h0;
                *(uint32_t*)&Cl[(size_t)row0 * Ntot + col] = l0;
                *(uint32_t*)&Ch[(size_t)(row0 + 8) * Ntot + col] = h1;
                *(uint32_t*)&Cl[(size_t)(row0 + 8) * Ntot + col] = l1;
            } else {
                *(float2*)&Cf[(size_t)row0 * Ntot + col] = make_float2(v0, v1);
                *(float2*)&Cf[(size_t)(row0 + 8) * Ntot + col] = make_float2(v2, v3);
            }
        }
    }
}

// ===================== tensor-core causal flash attention ==================
// CTA: 128 q-rows x 1 head. 8 warps x 16 rows. Double-buffered K/V stages.
// V row-major like K; PV B-frags via ldmatrix.trans. Longest-qt-first order.
#define A_KH   0
#define A_KL   16384
#define A_VH   32768
#define A_VL   49152
#define A_BUF  65536
#define ATT_SMEM 131072
#define C1 0.18033688011112042f   // 0.125 * log2(e)

__device__ __forceinline__ void attn_load_kv(
    uint32_t bufbase,
    const __nv_bfloat16* qkvh, const __nv_bfloat16* qkvl,
    int b, int h, int jt, int tid)
{
    #pragma unroll
    for (int j = 0; j < 8; j++) {
        int idx = tid + j * 256;
        int hl = idx >> 10, r = (idx >> 3) & 127, c = idx & 7;
        const __nv_bfloat16* src = (hl ? qkvl : qkvh)
            + (size_t)(b * SEQ + jt * 128 + r) * N1 + DIM + h * HD + c * 8;
        CP16(bufbase + hl * 16384 + r * 128 + ((c ^ (r & 7)) << 4), src);
    }
    #pragma unroll
    for (int j = 0; j < 8; j++) {
        int idx = tid + j * 256;
        int hl = idx >> 10, r = (idx >> 3) & 127, c = idx & 7;
        const __nv_bfloat16* src = (hl ? qkvl : qkvh)
            + (size_t)(b * SEQ + jt * 128 + r) * N1 + 2 * DIM + h * HD + c * 8;
        CP16(bufbase + A_VH + hl * 16384 + r * 128 + ((c ^ (r & 7)) << 4), src);
    }
}

__global__ __launch_bounds__(256, 1) void attn_mma(
    const __nv_bfloat16* __restrict__ qkvh, const __nv_bfloat16* __restrict__ qkvl,
    __nv_bfloat16* __restrict__ oh, __nv_bfloat16* __restrict__ ol)
{
    extern __shared__ char smem[];
    const uint32_t sb = smem_u32(smem);
    const int tid = threadIdx.x, lane = tid & 31, w = tid >> 5;
    const int qt = gridDim.x - 1 - blockIdx.x;   // longest-first
    const int h = blockIdx.y, b = blockIdx.z;
    const int nt = qt + 1;

    // ---- stage Q tile into buf0 K region, then to fragments ----
    #pragma unroll
    for (int j = 0; j < 8; j++) {
        int idx = tid + j * 256;
        int hl = idx >> 10, r = (idx >> 3) & 127, c = idx & 7;
        const __nv_bfloat16* src = (hl ? qkvl : qkvh)
            + (size_t)(b * SEQ + qt * 128 + r) * N1 + h * HD + c * 8;
        CP16(sb + hl * 16384 + r * 128 + ((c ^ (r & 7)) << 4), src);
    }
    CP_COMMIT(); CP_WAIT(0);
    __syncthreads();

    const int rowA = w * 16 + (lane & 15);
    const int clA = lane >> 4, xorA = rowA & 7;
    uint32_t qh[4][4], ql[4][4];
    #pragma unroll
    for (int ks = 0; ks < 4; ks++) {
        uint32_t off = (uint32_t)(rowA * 128 + ((((ks << 1) + clA) ^ xorA) << 4));
        LDSM4(qh[ks][0], qh[ks][1], qh[ks][2], qh[ks][3], sb + off);
        LDSM4(ql[ks][0], ql[ks][1], ql[ks][2], ql[ks][3], sb + 16384 + off);
    }
    __syncthreads();

    attn_load_kv(sb, qkvh, qkvl, b, h, 0, tid);
    CP_COMMIT();

    float m2[2] = {-1e30f, -1e30f}, lsum[2] = {0.f, 0.f};
    float o[8][4];
    #pragma unroll
    for (int nf = 0; nf < 8; nf++)
        #pragma unroll
        for (int q = 0; q < 4; q++) o[nf][q] = 0.f;

    const int rowB = ((lane >> 4) << 3) + (lane & 7);
    const int clB = (lane >> 3) & 1, xorB = lane & 7;
    const int vkr = (lane & 7) + ((lane >> 3) & 1) * 8;
    const int vdc = lane >> 4;

    for (int jt = 0; jt < nt; jt++) {
        CP_WAIT(0);
        __syncthreads();
        if (jt + 1 < nt) {
            attn_load_kv(sb + ((jt + 1) & 1) * A_BUF, qkvh, qkvl, b, h, jt + 1, tid);
            CP_COMMIT();
        }
        const uint32_t kb = sb + (jt & 1) * A_BUF;

        // ---- scores S = Q K^T ----
        float s[16][4];
        #pragma unroll
        for (int nf = 0; nf < 16; nf++)
            #pragma unroll
            for (int q = 0; q < 4; q++) s[nf][q] = 0.f;

        #pragma unroll
        for (int ks = 0; ks < 4; ks++) {
            #pragma unroll
            for (int nf2 = 0; nf2 < 8; nf2++) {
                uint32_t off = (uint32_t)((rowB + nf2 * 16) * 128 +
                               ((((ks << 1) + clB) ^ xorB) << 4));
                uint32_t kh0, kh1, kh2, kh3, kl0, kl1, kl2, kl3;
                LDSM4(kh0, kh1, kh2, kh3, kb + A_KH + off);
                LDSM4(kl0, kl1, kl2, kl3, kb + A_KL + off);
                MMA_BF16(s[nf2 * 2], qh[ks][0], qh[ks][1], qh[ks][2], qh[ks][3], kh0, kh1);
                MMA_BF16(s[nf2 * 2], qh[ks][0], qh[ks][1], qh[ks][2], qh[ks][3], kl0, kl1);
                MMA_BF16(s[nf2 * 2], ql[ks][0], ql[ks][1], ql[ks][2], ql[ks][3], kh0, kh1);
                MMA_BF16(s[nf2 * 2 + 1], qh[ks][0], qh[ks][1], qh[ks][2], qh[ks][3], kh2, kh3);
                MMA_BF16(s[nf2 * 2 + 1], qh[ks][0], qh[ks][1], qh[ks][2], qh[ks][3], kl2, kl3);
                MMA_BF16(s[nf2 * 2 + 1], ql[ks][0], ql[ks][1], ql[ks][2], ql[ks][3], kh2, kh3);
            }
        }

        // ---- causal mask (diagonal tile only) ----
        if (jt == qt) {
            const int r0l = w * 16 + (lane >> 2);
            #pragma unroll
            for (int nf = 0; nf < 16; nf++) {
                const int c0l = nf * 8 + (lane & 3) * 2;
                if (c0l     > r0l)     s[nf][0] = -3e38f;
                if (c0l + 1 > r0l)     s[nf][1] = -3e38f;
                if (c0l     > r0l + 8) s[nf][2] = -3e38f;
                if (c0l + 1 > r0l + 8) s[nf][3] = -3e38f;
            }
        }

        // ---- online softmax (base-2) ----
        float mx0 = -3e38f, mx1 = -3e38f;
        #pragma unroll
        for (int nf = 0; nf < 16; nf++) {
            mx0 = fmaxf(mx0, fmaxf(s[nf][0], s[nf][1]));
            mx1 = fmaxf(mx1, fmaxf(s[nf][2], s[nf][3]));
        }
        mx0 = fmaxf(mx0, __shfl_xor_sync(0xffffffffu, mx0, 1));
        mx0 = fmaxf(mx0, __shfl_xor_sync(0xffffffffu, mx0, 2));
        mx1 = fmaxf(mx1, __shfl_xor_sync(0xffffffffu, mx1, 1));
        mx1 = fmaxf(mx1, __shfl_xor_sync(0xffffffffu, mx1, 2));
        const float m2n0 = fmaxf(m2[0], mx0 * C1);
        const float m2n1 = fmaxf(m2[1], mx1 * C1);
        const float corr0 = exp2f(m2[0] - m2n0);
        const float corr1 = exp2f(m2[1] - m2n1);
        m2[0] = m2n0; m2[1] = m2n1;

        float rs0 = 0.f, rs1 = 0.f;
        #pragma unroll
        for (int nf = 0; nf < 16; nf++) {
            s[nf][0] = exp2f(fmaf(s[nf][0], C1, -m2n0)); rs0 += s[nf][0];
            s[nf][1] = exp2f(fmaf(s[nf][1], C1, -m2n0)); rs0 += s[nf][1];
            s[nf][2] = exp2f(fmaf(s[nf][2], C1, -m2n1)); rs1 += s[nf][2];
            s[nf][3] = exp2f(fmaf(s[nf][3], C1, -m2n1)); rs1 += s[nf][3];
        }
        rs0 += __shfl_xor_sync(0xffffffffu, rs0, 1);
        rs0 += __shfl_xor_sync(0xffffffffu, rs0, 2);
        rs1 += __shfl_xor_sync(0xffffffffu, rs1, 1);
        rs1 += __shfl_xor_sync(0xffffffffu, rs1, 2);
        lsum[0] = lsum[0] * corr0 + rs0;
        lsum[1] = lsum[1] * corr1 + rs1;
        #pragma unroll
        for (int nf = 0; nf < 8; nf++) {
            o[nf][0] *= corr0; o[nf][1] *= corr0;
            o[nf][2] *= corr1; o[nf][3] *= corr1;
        }

        // ---- O += P V ----
        #pragma unroll
        for (int kc = 0; kc < 8; kc++) {
            uint32_t pa0, pa1, pa2, pa3, pb0, pb1, pb2, pb3;
            pack_hl(s[2 * kc][0],     s[2 * kc][1],     pa0, pb0);
            pack_hl(s[2 * kc][2],     s[2 * kc][3],     pa1, pb1);
            pack_hl(s[2 * kc + 1][0], s[2 * kc + 1][1], pa2, pb2);
            pack_hl(s[2 * kc + 1][2], s[2 * kc + 1][3], pa3, pb3);
            const int kr = kc * 16 + vkr;
            #pragma unroll
            for (int nf2 = 0; nf2 < 4; nf2++) {
                uint32_t off = (uint32_t)(kr * 128 +
                               (((nf2 * 2 + vdc) ^ (kr & 7)) << 4));
                uint32_t vh0, vh1, vh2, vh3, vl0, vl1, vl2, vl3;
                LDSM4T(vh0, vh1, vh2, vh3, kb + A_VH + off);
                LDSM4T(vl0, vl1, vl2, vl3, kb + A_VL + off);
                MMA_BF16(o[nf2 * 2], pa0, pa1, pa2, pa3, vh0, vh1);
                MMA_BF16(o[nf2 * 2], pa0, pa1, pa2, pa3, vl0, vl1);
                MMA_BF16(o[nf2 * 2], pb0, pb1, pb2, pb3, vh0, vh1);
                MMA_BF16(o[nf2 * 2 + 1], pa0, pa1, pa2, pa3, vh2, vh3);
                MMA_BF16(o[nf2 * 2 + 1], pa0, pa1, pa2, pa3, vl2, vl3);
                MMA_BF16(o[nf2 * 2 + 1], pb0, pb1, pb2, pb3, vh2, vh3);
            }
        }
    }

    // ---- normalize + write bf16 hi/lo ----
    const float inv0 = 1.f / lsum[0], inv1 = 1.f / lsum[1];
    const size_t gr = (size_t)(b * SEQ + qt * 128 + w * 16 + (lane >> 2));
    const int colb = h * HD + (lane & 3) * 2;
    #pragma unroll
    for (int nf = 0; nf < 8; nf++) {
        const int col = colb + nf * 8;
        uint32_t h0, l0, h1, l1;
        pack_hl(o[nf][0] * inv0, o[nf][1] * inv0, h0, l0);
        pack_hl(o[nf][2] * inv1, o[nf][3] * inv1, h1, l1);
        *(uint32_t*)&oh[gr * DIM + col] = h0;
        *(uint32_t*)&ol[gr * DIM + col] = l0;
        *(uint32_t*)&oh[(gr + 8) * DIM + col] = h1;
        *(uint32_t*)&ol[(gr + 8) * DIM + col] = l1;
    }
}

// =============================== launch ====================================
extern "C" void kernel_launch(void* const* d_in, const int* in_sizes, int n_in,
                              void* d_out, int out_size)
{
    const float* x      = (const float*)d_in[0];
    const float* W_attn = (const float*)d_in[1];
    const float* b_attn = (const float*)d_in[2];
    const float* W_proj = (const float*)d_in[3];
    const float* b_proj = (const float*)d_in[4];
    float* out = (float*)d_out;

    __nv_bfloat16 *qkvh, *qkvl, *xh, *xl, *ahp, *alp, *wth, *wtl;
    cudaGetSymbolAddress((void**)&qkvh, g_qkvh);
    cudaGetSymbolAddress((void**)&qkvl, g_qkvl);
    cudaGetSymbolAddress((void**)&xh,  g_xh);
    cudaGetSymbolAddress((void**)&xl,  g_xl);
    cudaGetSymbolAddress((void**)&ahp, g_ah);
    cudaGetSymbolAddress((void**)&alp, g_al);
    cudaGetSymbolAddress((void**)&wth, g_wth);
    cudaGetSymbolAddress((void**)&wtl, g_wtl);

    static int attrs_set = 0;
    if (!attrs_set) {
        cudaFuncSetAttribute(gemm_mma<0>, cudaFuncAttributeMaxDynamicSharedMemorySize, GEMM_SMEM);
        cudaFuncSetAttribute(gemm_mma<1>, cudaFuncAttributeMaxDynamicSharedMemorySize, GEMM_SMEM);
        cudaFuncSetAttribute(attn_mma, cudaFuncAttributeMaxDynamicSharedMemorySize, ATT_SMEM);
        attrs_set = 1;
    }

    // 1) x -> bf16 hi/lo
    {
        int n4 = MROWS * KTOT / 4;
        split_fp32<<<(n4 + 255) / 256, 256>>>(x, xh, xl, n4);
    }
    // 2) W_attn -> transposed hi/lo
    transpose_split<<<dim3(N1 / 32, KTOT / 32), dim3(32, 8)>>>(W_attn, wth, wtl, KTOT, N1);
    // 3) qkv GEMM -> bf16 hi/lo
    gemm_mma<1><<<dim3(N1 / 128, MROWS / 128), 256, GEMM_SMEM>>>(
        xh, xl, wth, wtl, b_attn, nullptr, qkvh, qkvl, N1);
    // 4) attention (tensor cores)
    attn_mma<<<dim3(SEQ / 128, NH, BATCH), 256, ATT_SMEM>>>(
        qkvh, qkvl, ahp, alp);
    // 5) W_proj -> transposed hi/lo
    transpose_split<<<dim3(N2 / 32, KTOT / 32), dim3(32, 8)>>>(W_proj, wth, wtl, KTOT, N2);
    // 6) out GEMM (fp32 out)
    gemm_mma<0><<<dim3(N2 / 128, MROWS / 128), 256, GEMM_SMEM>>>(
        ahp, alp, wth, wtl, b_proj, out, nullptr, nullptr, N2);
}

// round 7
// speedup vs baseline: 1.7143x; 1.5905x over previous
#include <cuda_runtime.h>
#include <cuda_fp16.h>
#include <cstdint>
#include <cstddef>

// ---------------------------------------------------------------------------
// B=16, S=1024, DIM=768, H=12, HD=64 — fp16 tensor-core pipeline:
//   qkv(fp16) = x @ W_attn + b_attn    (2-term fp16 MMA: A*(Bh+Bl))
//   attn      = causal MHA             (single-term fp16 MMA, online softmax)
//   out       = attn @ W_proj + b_proj (2-term fp16 MMA, fp32 out)
// ---------------------------------------------------------------------------
#define BATCH 16
#define SEQ   1024
#define DIM   768
#define NH    12
#define HD    64
#define MROWS (BATCH * SEQ)
#define KTOT  768
#define N1    (3 * DIM)
#define N2    DIM

__device__ __half g_qkv16[MROWS * N1];
__device__ __half g_x16[MROWS * KTOT];
__device__ __half g_a16[MROWS * KTOT];
__device__ __half g_w1h[N1 * KTOT];
__device__ __half g_w1l[N1 * KTOT];
__device__ __half g_w2h[N2 * KTOT];
__device__ __half g_w2l[N2 * KTOT];

// ============================ PTX helpers ==================================
__device__ __forceinline__ uint32_t smem_u32(const void* p) {
    uint32_t a;
    asm("{ .reg .u64 t; cvta.to.shared.u64 t, %1; cvt.u32.u64 %0, t; }"
        : "=r"(a) : "l"(p));
    return a;
}

#define CP16(d, s) \
    asm volatile("cp.async.cg.shared.global [%0], [%1], 16;" :: "r"(d), "l"(s))
#define CP_COMMIT() asm volatile("cp.async.commit_group;" ::: "memory")
#define CP_WAIT(n)  asm volatile("cp.async.wait_group %0;" :: "n"(n) : "memory")

#define LDSM4(r0, r1, r2, r3, a) \
    asm volatile("ldmatrix.sync.aligned.m8n8.x4.shared.b16 {%0,%1,%2,%3}, [%4];" \
                 : "=r"(r0), "=r"(r1), "=r"(r2), "=r"(r3) : "r"(a))

#define LDSM4T(r0, r1, r2, r3, a) \
    asm volatile("ldmatrix.sync.aligned.m8n8.x4.trans.shared.b16 {%0,%1,%2,%3}, [%4];" \
                 : "=r"(r0), "=r"(r1), "=r"(r2), "=r"(r3) : "r"(a))

#define MMA_F16(d, a0, a1, a2, a3, b0, b1) \
    asm volatile("mma.sync.aligned.m16n8k16.row.col.f32.f16.f16.f32 " \
                 "{%0,%1,%2,%3}, {%4,%5,%6,%7}, {%8,%9}, {%0,%1,%2,%3};" \
                 : "+f"((d)[0]), "+f"((d)[1]), "+f"((d)[2]), "+f"((d)[3]) \
                 : "r"(a0), "r"(a1), "r"(a2), "r"(a3), "r"(b0), "r"(b1))

__device__ __forceinline__ uint32_t pack_h(float x, float y) {
    __half2 t = __float22half2_rn(make_float2(x, y));
    return *(uint32_t*)&t;
}

// ======================= conversion kernels ================================
__global__ __launch_bounds__(256) void cvt_f16(
    const float* __restrict__ in, __half* __restrict__ out, int n4)
{
    int i = blockIdx.x * 256 + threadIdx.x;
    if (i >= n4) return;
    float4 v = ((const float4*)in)[i];
    ((uint32_t*)out)[i * 2 + 0] = pack_h(v.x, v.y);
    ((uint32_t*)out)[i * 2 + 1] = pack_h(v.z, v.w);
}

// W[K][N] -> transposed hi/lo fp16 [N][K]
__global__ __launch_bounds__(256) void transpose_split(
    const float* __restrict__ W, __half* __restrict__ Th,
    __half* __restrict__ Tl, int K, int N)
{
    __shared__ float tile[32][33];
    int tx = threadIdx.x, ty = threadIdx.y;
    int nx = blockIdx.x * 32 + tx;
    int ky = blockIdx.y * 32 + ty;
    #pragma unroll
    for (int j = 0; j < 32; j += 8)
        tile[ty + j][tx] = W[(size_t)(ky + j) * N + nx];
    __syncthreads();
    int kx = blockIdx.y * 32 + tx;
    int ny = blockIdx.x * 32 + ty;
    #pragma unroll
    for (int j = 0; j < 32; j += 8) {
        float v = tile[tx][ty + j];
        __half h = __float2half(v);
        __half l = __float2half(v - __half2float(h));
        Th[(size_t)(ny + j) * K + kx] = h;
        Tl[(size_t)(ny + j) * K + kx] = l;
    }
}

// ================== HMMA GEMM (fp16, 2-term: A*(Bh+Bl)) ====================
// 128x128 tile, BK=64, 4 stages, 256 threads (8 warps, 32x64 warp tiles).
#define NSTG    4
#define NIT     12
#define T_A     0
#define T_BH    16384
#define T_BL    32768
#define STG     49152
#define GEMM_SMEM (NSTG * STG)     // 196608

__device__ __forceinline__ void stage_load(
    uint32_t sstage, const __half* A, const __half* Bh, const __half* Bl,
    int mtile, int ntile, int kiter, int tid)
{
    #pragma unroll
    for (int j = 0; j < 4; j++) {
        int idx = tid + j * 256;
        int r = idx >> 3, c = idx & 7;
        uint32_t so = (uint32_t)(r * 128 + ((c ^ (r & 7)) << 4));
        CP16(sstage + T_A + so,
             (const char*)(A + (size_t)(mtile * 128 + r) * KTOT + kiter * 64 + c * 8));
    }
    #pragma unroll
    for (int j = 0; j < 4; j++) {
        int idx = tid + j * 256;
        int r = idx >> 3, c = idx & 7;
        uint32_t so = (uint32_t)(r * 128 + ((c ^ (r & 7)) << 4));
        size_t g = (size_t)(ntile * 128 + r) * KTOT + kiter * 64 + c * 8;
        CP16(sstage + T_BH + so, (const char*)(Bh + g));
        CP16(sstage + T_BL + so, (const char*)(Bl + g));
    }
}

template<int OUT16>
__global__ __launch_bounds__(256) void gemm_mma(
    const __half* __restrict__ A,
    const __half* __restrict__ Bh, const __half* __restrict__ Bl,
    const float* __restrict__ bias, float* __restrict__ Cf,
    __half* __restrict__ Ch, int Ntot)
{
    extern __shared__ char smem[];
    const uint32_t sb = smem_u32(smem);
    const int tid = threadIdx.x, lane = tid & 31, wid = tid >> 5;
    const int mtile = blockIdx.y, ntile = blockIdx.x;
    const int wm = (wid & 3) * 32;
    const int wn = (wid >> 2) * 64;

    const int rowA  = wm + (lane & 15);
    const int xorA  = rowA & 7;
    const int clA   = lane >> 4;
    const int rowB  = wn + ((lane >> 4) << 3) + (lane & 7);
    const int xorB  = rowB & 7;
    const int clB   = (lane >> 3) & 1;

    float acc[2][8][4];
    #pragma unroll
    for (int mf = 0; mf < 2; mf++)
        #pragma unroll
        for (int nf = 0; nf < 8; nf++)
            #pragma unroll
            for (int q = 0; q < 4; q++) acc[mf][nf][q] = 0.f;

    stage_load(sb + 0 * STG, A, Bh, Bl, mtile, ntile, 0, tid); CP_COMMIT();
    stage_load(sb + 1 * STG, A, Bh, Bl, mtile, ntile, 1, tid); CP_COMMIT();
    stage_load(sb + 2 * STG, A, Bh, Bl, mtile, ntile, 2, tid); CP_COMMIT();

    for (int i = 0; i < NIT; i++) {
        if (i + 3 < NIT) {
            stage_load(sb + ((i + 3) & 3) * STG, A, Bh, Bl, mtile, ntile, i + 3, tid);
            CP_COMMIT();
            CP_WAIT(3);
        } else if (i + 2 < NIT) {
            CP_WAIT(2);
        } else if (i + 1 < NIT) {
            CP_WAIT(1);
        } else {
            CP_WAIT(0);
        }
        __syncthreads();

        const uint32_t st = sb + (i & 3) * STG;
        #pragma unroll
        for (int ks = 0; ks < 4; ks++) {
            uint32_t ar[2][4], bh[8][2], bl[8][2];
            #pragma unroll
            for (int mf = 0; mf < 2; mf++) {
                uint32_t off = (uint32_t)((rowA + mf * 16) * 128 +
                               ((((ks << 1) + clA) ^ xorA) << 4));
                LDSM4(ar[mf][0], ar[mf][1], ar[mf][2], ar[mf][3], st + T_A + off);
            }
            #pragma unroll
            for (int nf2 = 0; nf2 < 4; nf2++) {
                uint32_t off = (uint32_t)((rowB + nf2 * 16) * 128 +
                               ((((ks << 1) + clB) ^ xorB) << 4));
                LDSM4(bh[nf2 * 2][0], bh[nf2 * 2][1],
                      bh[nf2 * 2 + 1][0], bh[nf2 * 2 + 1][1], st + T_BH + off);
                LDSM4(bl[nf2 * 2][0], bl[nf2 * 2][1],
                      bl[nf2 * 2 + 1][0], bl[nf2 * 2 + 1][1], st + T_BL + off);
            }
            #pragma unroll
            for (int mf = 0; mf < 2; mf++)
                #pragma unroll
                for (int nf = 0; nf < 8; nf++) {
                    MMA_F16(acc[mf][nf], ar[mf][0], ar[mf][1], ar[mf][2], ar[mf][3],
                            bh[nf][0], bh[nf][1]);
                    MMA_F16(acc[mf][nf], ar[mf][0], ar[mf][1], ar[mf][2], ar[mf][3],
                            bl[nf][0], bl[nf][1]);
                }
        }
        __syncthreads();
    }

    #pragma unroll
    for (int mf = 0; mf < 2; mf++) {
        #pragma unroll
        for (int nf = 0; nf < 8; nf++) {
            const int col = ntile * 128 + wn + nf * 8 + (lane & 3) * 2;
            const int row0 = mtile * 128 + wm + mf * 16 + (lane >> 2);
            const float b0 = bias[col], b1 = bias[col + 1];
            float v0 = acc[mf][nf][0] + b0, v1 = acc[mf][nf][1] + b1;
            float v2 = acc[mf][nf][2] + b0, v3 = acc[mf][nf][3] + b1;
            if (OUT16) {
                *(uint32_t*)&Ch[(size_t)row0 * Ntot + col] = pack_h(v0, v1);
                *(uint32_t*)&Ch[(size_t)(row0 + 8) * Ntot + col] = pack_h(v2, v3);
            } else {
                *(float2*)&Cf[(size_t)row0 * Ntot + col] = make_float2(v0, v1);
                *(float2*)&Cf[(size_t)(row0 + 8) * Ntot + col] = make_float2(v2, v3);
            }
        }
    }
}

// ============== tensor-core causal flash attention (fp16) ==================
// CTA: 128 q-rows x 1 head, 8 warps. Q 16KB + 2 x 32KB K/V double buffer.
#define AQ_OFF   0
#define ABUF0    16384
#define A_V      16384            // V offset within a buffer
#define A_BUF    32768
#define ATT_SMEM 81920
#define C1 0.18033688011112042f   // 0.125 * log2(e)

__device__ __forceinline__ void attn_load_kv(
    uint32_t bufbase, const __half* qkv, int b, int h, int jt, int tid)
{
    #pragma unroll
    for (int j = 0; j < 8; j++) {
        int idx = tid + j * 256;
        if (idx < 1024) {       // K tile
            int r = idx >> 3, c = idx & 7;
            const __half* src = qkv
                + (size_t)(b * SEQ + jt * 128 + r) * N1 + DIM + h * HD + c * 8;
            CP16(bufbase + r * 128 + ((c ^ (r & 7)) << 4), src);
        } else {                // V tile
            int rem = idx - 1024;
            int r = rem >> 3, c = rem & 7;
            const __half* src = qkv
                + (size_t)(b * SEQ + jt * 128 + r) * N1 + 2 * DIM + h * HD + c * 8;
            CP16(bufbase + A_V + r * 128 + ((c ^ (r & 7)) << 4), src);
        }
    }
}

__global__ __launch_bounds__(256, 1) void attn_mma(
    const __half* __restrict__ qkv, __half* __restrict__ outa)
{
    extern __shared__ char smem[];
    const uint32_t sb = smem_u32(smem);
    const int tid = threadIdx.x, lane = tid & 31, w = tid >> 5;
    const int qt = gridDim.x - 1 - blockIdx.x;   // longest-first
    const int h = blockIdx.y, b = blockIdx.z;
    const int nt = qt + 1;

    // ---- stage Q tile, then to fragments ----
    #pragma unroll
    for (int j = 0; j < 4; j++) {
        int idx = tid + j * 256;
        int r = idx >> 3, c = idx & 7;
        const __half* src = qkv
            + (size_t)(b * SEQ + qt * 128 + r) * N1 + h * HD + c * 8;
        CP16(sb + AQ_OFF + r * 128 + ((c ^ (r & 7)) << 4), src);
    }
    CP_COMMIT(); CP_WAIT(0);
    __syncthreads();

    const int rowA = w * 16 + (lane & 15);
    const int clA = lane >> 4, xorA = rowA & 7;
    uint32_t qf[4][4];
    #pragma unroll
    for (int ks = 0; ks < 4; ks++) {
        uint32_t off = (uint32_t)(rowA * 128 + ((((ks << 1) + clA) ^ xorA) << 4));
        LDSM4(qf[ks][0], qf[ks][1], qf[ks][2], qf[ks][3], sb + AQ_OFF + off);
    }

    attn_load_kv(sb + ABUF0, qkv, b, h, 0, tid);
    CP_COMMIT();

    float m2[2] = {-1e30f, -1e30f}, lsum[2] = {0.f, 0.f};
    float o[8][4];
    #pragma unroll
    for (int nf = 0; nf < 8; nf++)
        #pragma unroll
        for (int q = 0; q < 4; q++) o[nf][q] = 0.f;

    const int rowB = ((lane >> 4) << 3) + (lane & 7);
    const int clB = (lane >> 3) & 1, xorB = lane & 7;
    const int vkr = (lane & 7) + ((lane >> 3) & 1) * 8;
    const int vdc = lane >> 4;

    for (int jt = 0; jt < nt; jt++) {
        CP_WAIT(0);
        __syncthreads();
        if (jt + 1 < nt) {
            attn_load_kv(sb + ABUF0 + ((jt + 1) & 1) * A_BUF, qkv, b, h, jt + 1, tid);
            CP_COMMIT();
        }
        const uint32_t kb = sb + ABUF0 + (jt & 1) * A_BUF;

        // ---- scores S = Q K^T ----
        float s[16][4];
        #pragma unroll
        for (int nf = 0; nf < 16; nf++)
            #pragma unroll
            for (int q = 0; q < 4; q++) s[nf][q] = 0.f;

        #pragma unroll
        for (int ks = 0; ks < 4; ks++) {
            #pragma unroll
            for (int nf2 = 0; nf2 < 8; nf2++) {
                uint32_t off = (uint32_t)((rowB + nf2 * 16) * 128 +
                               ((((ks << 1) + clB) ^ xorB) << 4));
                uint32_t k0, k1, k2, k3;
                LDSM4(k0, k1, k2, k3, kb + off);
                MMA_F16(s[nf2 * 2],     qf[ks][0], qf[ks][1], qf[ks][2], qf[ks][3], k0, k1);
                MMA_F16(s[nf2 * 2 + 1], qf[ks][0], qf[ks][1], qf[ks][2], qf[ks][3], k2, k3);
            }
        }

        // ---- causal mask (diagonal tile only) ----
        if (jt == qt) {
            const int r0l = w * 16 + (lane >> 2);
            #pragma unroll
            for (int nf = 0; nf < 16; nf++) {
                const int c0l = nf * 8 + (lane & 3) * 2;
                if (c0l     > r0l)     s[nf][0] = -3e38f;
                if (c0l + 1 > r0l)     s[nf][1] = -3e38f;
                if (c0l     > r0l + 8) s[nf][2] = -3e38f;
                if (c0l + 1 > r0l + 8) s[nf][3] = -3e38f;
            }
        }

        // ---- online softmax (base-2) ----
        float mx0 = -3e38f, mx1 = -3e38f;
        #pragma unroll
        for (int nf = 0; nf < 16; nf++) {
            mx0 = fmaxf(mx0, fmaxf(s[nf][0], s[nf][1]));
            mx1 = fmaxf(mx1, fmaxf(s[nf][2], s[nf][3]));
        }
        mx0 = fmaxf(mx0, __shfl_xor_sync(0xffffffffu, mx0, 1));
        mx0 = fmaxf(mx0, __shfl_xor_sync(0xffffffffu, mx0, 2));
        mx1 = fmaxf(mx1, __shfl_xor_sync(0xffffffffu, mx1, 1));
        mx1 = fmaxf(mx1, __shfl_xor_sync(0xffffffffu, mx1, 2));
        const float m2n0 = fmaxf(m2[0], mx0 * C1);
        const float m2n1 = fmaxf(m2[1], mx1 * C1);
        const float corr0 = exp2f(m2[0] - m2n0);
        const float corr1 = exp2f(m2[1] - m2n1);
        m2[0] = m2n0; m2[1] = m2n1;

        float rs0 = 0.f, rs1 = 0.f;
        #pragma unroll
        for (int nf = 0; nf < 16; nf++) {
            s[nf][0] = exp2f(fmaf(s[nf][0], C1, -m2n0)); rs0 += s[nf][0];
            s[nf][1] = exp2f(fmaf(s[nf][1], C1, -m2n0)); rs0 += s[nf][1];
            s[nf][2] = exp2f(fmaf(s[nf][2], C1, -m2n1)); rs1 += s[nf][2];
            s[nf][3] = exp2f(fmaf(s[nf][3], C1, -m2n1)); rs1 += s[nf][3];
        }
        rs0 += __shfl_xor_sync(0xffffffffu, rs0, 1);
        rs0 += __shfl_xor_sync(0xffffffffu, rs0, 2);
        rs1 += __shfl_xor_sync(0xffffffffu, rs1, 1);
        rs1 += __shfl_xor_sync(0xffffffffu, rs1, 2);
        lsum[0] = lsum[0] * corr0 + rs0;
        lsum[1] = lsum[1] * corr1 + rs1;
        #pragma unroll
        for (int nf = 0; nf < 8; nf++) {
            o[nf][0] *= corr0; o[nf][1] *= corr0;
            o[nf][2] *= corr1; o[nf][3] *= corr1;
        }

        // ---- O += P V (P packed fp16 in-register; V via ldmatrix.trans) ----
        #pragma unroll
        for (int kc = 0; kc < 8; kc++) {
            uint32_t pa0 = pack_h(s[2 * kc][0],     s[2 * kc][1]);
            uint32_t pa1 = pack_h(s[2 * kc][2],     s[2 * kc][3]);
            uint32_t pa2 = pack_h(s[2 * kc + 1][0], s[2 * kc + 1][1]);
            uint32_t pa3 = pack_h(s[2 * kc + 1][2], s[2 * kc + 1][3]);
            const int kr = kc * 16 + vkr;
            #pragma unroll
            for (int nf2 = 0; nf2 < 4; nf2++) {
                uint32_t off = (uint32_t)(kr * 128 +
                               (((nf2 * 2 + vdc) ^ (kr & 7)) << 4));
                uint32_t v0, v1, v2, v3;
                LDSM4T(v0, v1, v2, v3, kb + A_V + off);
                MMA_F16(o[nf2 * 2],     pa0, pa1, pa2, pa3, v0, v1);
                MMA_F16(o[nf2 * 2 + 1], pa0, pa1, pa2, pa3, v2, v3);
            }
        }
    }

    // ---- normalize + write fp16 ----
    const float inv0 = 1.f / lsum[0], inv1 = 1.f / lsum[1];
    const size_t gr = (size_t)(b * SEQ + qt * 128 + w * 16 + (lane >> 2));
    const int colb = h * HD + (lane & 3) * 2;
    #pragma unroll
    for (int nf = 0; nf < 8; nf++) {
        const int col = colb + nf * 8;
        *(uint32_t*)&outa[gr * DIM + col] = pack_h(o[nf][0] * inv0, o[nf][1] * inv0);
        *(uint32_t*)&outa[(gr + 8) * DIM + col] = pack_h(o[nf][2] * inv1, o[nf][3] * inv1);
    }
}

// =============================== launch ====================================
extern "C" void kernel_launch(void* const* d_in, const int* in_sizes, int n_in,
                              void* d_out, int out_size)
{
    const float* x      = (const float*)d_in[0];
    const float* W_attn = (const float*)d_in[1];
    const float* b_attn = (const float*)d_in[2];
    const float* W_proj = (const float*)d_in[3];
    const float* b_proj = (const float*)d_in[4];
    float* out = (float*)d_out;

    __half *qkv16, *x16, *a16, *w1h, *w1l, *w2h, *w2l;
    cudaGetSymbolAddress((void**)&qkv16, g_qkv16);
    cudaGetSymbolAddress((void**)&x16, g_x16);
    cudaGetSymbolAddress((void**)&a16, g_a16);
    cudaGetSymbolAddress((void**)&w1h, g_w1h);
    cudaGetSymbolAddress((void**)&w1l, g_w1l);
    cudaGetSymbolAddress((void**)&w2h, g_w2h);
    cudaGetSymbolAddress((void**)&w2l, g_w2l);

    static int attrs_set = 0;
    if (!attrs_set) {
        cudaFuncSetAttribute(gemm_mma<0>, cudaFuncAttributeMaxDynamicSharedMemorySize, GEMM_SMEM);
        cudaFuncSetAttribute(gemm_mma<1>, cudaFuncAttributeMaxDynamicSharedMemorySize, GEMM_SMEM);
        cudaFuncSetAttribute(attn_mma, cudaFuncAttributeMaxDynamicSharedMemorySize, ATT_SMEM);
        attrs_set = 1;
    }

    // 1) x -> fp16
    {
        int n4 = MROWS * KTOT / 4;
        cvt_f16<<<(n4 + 255) / 256, 256>>>(x, x16, n4);
    }
    // 2) W_attn -> transposed hi/lo fp16
    transpose_split<<<dim3(N1 / 32, KTOT / 32), dim3(32, 8)>>>(W_attn, w1h, w1l, KTOT, N1);
    // 3) W_proj -> transposed hi/lo fp16
    transpose_split<<<dim3(N2 / 32, KTOT / 32), dim3(32, 8)>>>(W_proj, w2h, w2l, KTOT, N2);
    // 4) qkv GEMM (fp16 out)
    gemm_mma<1><<<dim3(N1 / 128, MROWS / 128), 256, GEMM_SMEM>>>(
        x16, w1h, w1l, b_attn, nullptr, qkv16, N1);
    // 5) attention
    attn_mma<<<dim3(SEQ / 128, NH, BATCH), 256, ATT_SMEM>>>(qkv16, a16);
    // 6) out GEMM (fp32 out)
    gemm_mma<0><<<dim3(N2 / 128, MROWS / 128), 256, GEMM_SMEM>>>(
        a16, w2h, w2l, b_proj, out, nullptr, N2);
}

// round 8
// speedup vs baseline: 2.6132x; 1.5243x over previous
#include <cuda_runtime.h>
#include <cuda_fp16.h>
#include <cstdint>
#include <cstddef>

// ---------------------------------------------------------------------------
// B=16, S=1024, DIM=768, H=12, HD=64 — fp16 tensor-core pipeline:
//   qkv(fp16) = x @ W_attn + b_attn    (single-term fp16 MMA, fp32 accum)
//   attn      = causal MHA             (fp16 MMA, online softmax)
//   out       = attn @ W_proj + b_proj (single-term fp16 MMA, fp32 out)
// ---------------------------------------------------------------------------
#define BATCH 16
#define SEQ   1024
#define DIM   768
#define NH    12
#define HD    64
#define MROWS (BATCH * SEQ)
#define KTOT  768
#define N1    (3 * DIM)
#define N2    DIM

__device__ __half g_qkv16[MROWS * N1];
__device__ __half g_x16[MROWS * KTOT];
__device__ __half g_a16[MROWS * KTOT];
__device__ __half g_w1[N1 * KTOT];
__device__ __half g_w2[N2 * KTOT];

// ============================ PTX helpers ==================================
__device__ __forceinline__ uint32_t smem_u32(const void* p) {
    uint32_t a;
    asm("{ .reg .u64 t; cvta.to.shared.u64 t, %1; cvt.u32.u64 %0, t; }"
        : "=r"(a) : "l"(p));
    return a;
}

#define CP16(d, s) \
    asm volatile("cp.async.cg.shared.global [%0], [%1], 16;" :: "r"(d), "l"(s))
#define CP_COMMIT() asm volatile("cp.async.commit_group;" ::: "memory")
#define CP_WAIT(n)  asm volatile("cp.async.wait_group %0;" :: "n"(n) : "memory")

#define LDSM4(r0, r1, r2, r3, a) \
    asm volatile("ldmatrix.sync.aligned.m8n8.x4.shared.b16 {%0,%1,%2,%3}, [%4];" \
                 : "=r"(r0), "=r"(r1), "=r"(r2), "=r"(r3) : "r"(a))

#define LDSM4T(r0, r1, r2, r3, a) \
    asm volatile("ldmatrix.sync.aligned.m8n8.x4.trans.shared.b16 {%0,%1,%2,%3}, [%4];" \
                 : "=r"(r0), "=r"(r1), "=r"(r2), "=r"(r3) : "r"(a))

#define MMA_F16(d, a0, a1, a2, a3, b0, b1) \
    asm volatile("mma.sync.aligned.m16n8k16.row.col.f32.f16.f16.f32 " \
                 "{%0,%1,%2,%3}, {%4,%5,%6,%7}, {%8,%9}, {%0,%1,%2,%3};" \
                 : "+f"((d)[0]), "+f"((d)[1]), "+f"((d)[2]), "+f"((d)[3]) \
                 : "r"(a0), "r"(a1), "r"(a2), "r"(a3), "r"(b0), "r"(b1))

__device__ __forceinline__ uint32_t pack_h(float x, float y) {
    __half2 t = __float22half2_rn(make_float2(x, y));
    return *(uint32_t*)&t;
}

// ======================= conversion kernels ================================
__global__ __launch_bounds__(256) void cvt_f16(
    const float* __restrict__ in, __half* __restrict__ out, int n4)
{
    int i = blockIdx.x * 256 + threadIdx.x;
    if (i >= n4) return;
    float4 v = ((const float4*)in)[i];
    ((uint32_t*)out)[i * 2 + 0] = pack_h(v.x, v.y);
    ((uint32_t*)out)[i * 2 + 1] = pack_h(v.z, v.w);
}

// W[K][N] -> transposed fp16 [N][K]
__global__ __launch_bounds__(256) void transpose_f16(
    const float* __restrict__ W, __half* __restrict__ T, int K, int N)
{
    __shared__ float tile[32][33];
    int tx = threadIdx.x, ty = threadIdx.y;
    int nx = blockIdx.x * 32 + tx;
    int ky = blockIdx.y * 32 + ty;
    #pragma unroll
    for (int j = 0; j < 32; j += 8)
        tile[ty + j][tx] = W[(size_t)(ky + j) * N + nx];
    __syncthreads();
    int kx = blockIdx.y * 32 + tx;
    int ny = blockIdx.x * 32 + ty;
    #pragma unroll
    for (int j = 0; j < 32; j += 8)
        T[(size_t)(ny + j) * K + kx] = __float2half(tile[tx][ty + j]);
}

// ================== HMMA GEMM (single-term fp16) ===========================
// 128x128 tile, BK=64, 3 stages x 32KB, 256 threads, 2 CTAs/SM.
#define NSTG    3
#define NIT     12
#define T_A     0
#define T_B     16384
#define STG     32768
#define GEMM_SMEM (NSTG * STG)     // 98304

__device__ __forceinline__ void stage_load(
    uint32_t sstage, const __half* A, const __half* B,
    int mtile, int ntile, int kiter, int tid)
{
    #pragma unroll
    for (int j = 0; j < 4; j++) {
        int idx = tid + j * 256;
        int r = idx >> 3, c = idx & 7;
        uint32_t so = (uint32_t)(r * 128 + ((c ^ (r & 7)) << 4));
        CP16(sstage + T_A + so,
             (const char*)(A + (size_t)(mtile * 128 + r) * KTOT + kiter * 64 + c * 8));
        CP16(sstage + T_B + so,
             (const char*)(B + (size_t)(ntile * 128 + r) * KTOT + kiter * 64 + c * 8));
    }
}

template<int OUT16>
__global__ __launch_bounds__(256, 2) void gemm_mma(
    const __half* __restrict__ A, const __half* __restrict__ B,
    const float* __restrict__ bias, float* __restrict__ Cf,
    __half* __restrict__ Ch, int Ntot)
{
    extern __shared__ char smem[];
    const uint32_t sb = smem_u32(smem);
    const int tid = threadIdx.x, lane = tid & 31, wid = tid >> 5;
    const int mtile = blockIdx.y, ntile = blockIdx.x;
    const int wm = (wid & 3) * 32;
    const int wn = (wid >> 2) * 64;

    const int rowA  = wm + (lane & 15);
    const int xorA  = rowA & 7;
    const int clA   = lane >> 4;
    const int rowB  = wn + ((lane >> 4) << 3) + (lane & 7);
    const int xorB  = rowB & 7;
    const int clB   = (lane >> 3) & 1;

    float acc[2][8][4];
    #pragma unroll
    for (int mf = 0; mf < 2; mf++)
        #pragma unroll
        for (int nf = 0; nf < 8; nf++)
            #pragma unroll
            for (int q = 0; q < 4; q++) acc[mf][nf][q] = 0.f;

    stage_load(sb + 0 * STG, A, B, mtile, ntile, 0, tid); CP_COMMIT();
    stage_load(sb + 1 * STG, A, B, mtile, ntile, 1, tid); CP_COMMIT();

    for (int i = 0; i < NIT; i++) {
        if (i + 2 < NIT) {
            stage_load(sb + ((i + 2) % NSTG) * STG, A, B, mtile, ntile, i + 2, tid);
            CP_COMMIT();
            CP_WAIT(2);
        } else if (i + 1 < NIT) {
            CP_WAIT(1);
        } else {
            CP_WAIT(0);
        }
        __syncthreads();

        const uint32_t st = sb + (i % NSTG) * STG;
        #pragma unroll
        for (int ks = 0; ks < 4; ks++) {
            uint32_t ar[2][4], br[8][2];
            #pragma unroll
            for (int mf = 0; mf < 2; mf++) {
                uint32_t off = (uint32_t)((rowA + mf * 16) * 128 +
                               ((((ks << 1) + clA) ^ xorA) << 4));
                LDSM4(ar[mf][0], ar[mf][1], ar[mf][2], ar[mf][3], st + T_A + off);
            }
            #pragma unroll
            for (int nf2 = 0; nf2 < 4; nf2++) {
                uint32_t off = (uint32_t)((rowB + nf2 * 16) * 128 +
                               ((((ks << 1) + clB) ^ xorB) << 4));
                LDSM4(br[nf2 * 2][0], br[nf2 * 2][1],
                      br[nf2 * 2 + 1][0], br[nf2 * 2 + 1][1], st + T_B + off);
            }
            #pragma unroll
            for (int mf = 0; mf < 2; mf++)
                #pragma unroll
                for (int nf = 0; nf < 8; nf++)
                    MMA_F16(acc[mf][nf], ar[mf][0], ar[mf][1], ar[mf][2], ar[mf][3],
                            br[nf][0], br[nf][1]);
        }
        __syncthreads();
    }

    #pragma unroll
    for (int mf = 0; mf < 2; mf++) {
        #pragma unroll
        for (int nf = 0; nf < 8; nf++) {
            const int col = ntile * 128 + wn + nf * 8 + (lane & 3) * 2;
            const int row0 = mtile * 128 + wm + mf * 16 + (lane >> 2);
            const float b0 = bias[col], b1 = bias[col + 1];
            float v0 = acc[mf][nf][0] + b0, v1 = acc[mf][nf][1] + b1;
            float v2 = acc[mf][nf][2] + b0, v3 = acc[mf][nf][3] + b1;
            if (OUT16) {
                *(uint32_t*)&Ch[(size_t)row0 * Ntot + col] = pack_h(v0, v1);
                *(uint32_t*)&Ch[(size_t)(row0 + 8) * Ntot + col] = pack_h(v2, v3);
            } else {
                *(float2*)&Cf[(size_t)row0 * Ntot + col] = make_float2(v0, v1);
                *(float2*)&Cf[(size_t)(row0 + 8) * Ntot + col] = make_float2(v2, v3);
            }
        }
    }
}

// ============== tensor-core causal flash attention (fp16) ==================
// CTA: 128 q-rows x 1 head, 8 warps. Q 16KB + 2 x 32KB K/V double buffer.
#define AQ_OFF   0
#define ABUF0    16384
#define A_V      16384            // V offset within a buffer
#define A_BUF    32768
#define ATT_SMEM 81920
#define C1 0.18033688011112042f   // 0.125 * log2(e)

__device__ __forceinline__ void attn_load_kv(
    uint32_t bufbase, const __half* qkv, int b, int h, int jt, int tid)
{
    #pragma unroll
    for (int j = 0; j < 8; j++) {
        int idx = tid + j * 256;
        if (idx < 1024) {       // K tile
            int r = idx >> 3, c = idx & 7;
            const __half* src = qkv
                + (size_t)(b * SEQ + jt * 128 + r) * N1 + DIM + h * HD + c * 8;
            CP16(bufbase + r * 128 + ((c ^ (r & 7)) << 4), src);
        } else {                // V tile
            int rem = idx - 1024;
            int r = rem >> 3, c = rem & 7;
            const __half* src = qkv
                + (size_t)(b * SEQ + jt * 128 + r) * N1 + 2 * DIM + h * HD + c * 8;
            CP16(bufbase + A_V + r * 128 + ((c ^ (r & 7)) << 4), src);
        }
    }
}

__global__ __launch_bounds__(256, 1) void attn_mma(
    const __half* __restrict__ qkv, __half* __restrict__ outa)
{
    extern __shared__ char smem[];
    const uint32_t sb = smem_u32(smem);
    const int tid = threadIdx.x, lane = tid & 31, w = tid >> 5;
    const int qt = gridDim.x - 1 - blockIdx.x;   // longest-first
    const int h = blockIdx.y, b = blockIdx.z;
    const int nt = qt + 1;

    // ---- stage Q tile, then to fragments ----
    #pragma unroll
    for (int j = 0; j < 4; j++) {
        int idx = tid + j * 256;
        int r = idx >> 3, c = idx & 7;
        const __half* src = qkv
            + (size_t)(b * SEQ + qt * 128 + r) * N1 + h * HD + c * 8;
        CP16(sb + AQ_OFF + r * 128 + ((c ^ (r & 7)) << 4), src);
    }
    CP_COMMIT(); CP_WAIT(0);
    __syncthreads();

    const int rowA = w * 16 + (lane & 15);
    const int clA = lane >> 4, xorA = rowA & 7;
    uint32_t qf[4][4];
    #pragma unroll
    for (int ks = 0; ks < 4; ks++) {
        uint32_t off = (uint32_t)(rowA * 128 + ((((ks << 1) + clA) ^ xorA) << 4));
        LDSM4(qf[ks][0], qf[ks][1], qf[ks][2], qf[ks][3], sb + AQ_OFF + off);
    }

    attn_load_kv(sb + ABUF0, qkv, b, h, 0, tid);
    CP_COMMIT();

    float m2[2] = {-1e30f, -1e30f}, lsum[2] = {0.f, 0.f};
    float o[8][4];
    #pragma unroll
    for (int nf = 0; nf < 8; nf++)
        #pragma unroll
        for (int q = 0; q < 4; q++) o[nf][q] = 0.f;

    const int rowB = ((lane >> 4) << 3) + (lane & 7);
    const int clB = (lane >> 3) & 1, xorB = lane & 7;
    const int vkr = (lane & 7) + ((lane >> 3) & 1) * 8;
    const int vdc = lane >> 4;

    for (int jt = 0; jt < nt; jt++) {
        CP_WAIT(0);
        __syncthreads();
        if (jt + 1 < nt) {
            attn_load_kv(sb + ABUF0 + ((jt + 1) & 1) * A_BUF, qkv, b, h, jt + 1, tid);
            CP_COMMIT();
        }
        const uint32_t kb = sb + ABUF0 + (jt & 1) * A_BUF;

        // ---- scores S = Q K^T ----
        float s[16][4];
        #pragma unroll
        for (int nf = 0; nf < 16; nf++)
            #pragma unroll
            for (int q = 0; q < 4; q++) s[nf][q] = 0.f;

        #pragma unroll
        for (int ks = 0; ks < 4; ks++) {
            #pragma unroll
            for (int nf2 = 0; nf2 < 8; nf2++) {
                uint32_t off = (uint32_t)((rowB + nf2 * 16) * 128 +
                               ((((ks << 1) + clB) ^ xorB) << 4));
                uint32_t k0, k1, k2, k3;
                LDSM4(k0, k1, k2, k3, kb + off);
                MMA_F16(s[nf2 * 2],     qf[ks][0], qf[ks][1], qf[ks][2], qf[ks][3], k0, k1);
                MMA_F16(s[nf2 * 2 + 1], qf[ks][0], qf[ks][1], qf[ks][2], qf[ks][3], k2, k3);
            }
        }

        // ---- causal mask (diagonal tile only) ----
        if (jt == qt) {
            const int r0l = w * 16 + (lane >> 2);
            #pragma unroll
            for (int nf = 0; nf < 16; nf++) {
                const int c0l = nf * 8 + (lane & 3) * 2;
                if (c0l     > r0l)     s[nf][0] = -3e38f;
                if (c0l + 1 > r0l)     s[nf][1] = -3e38f;
                if (c0l     > r0l + 8) s[nf][2] = -3e38f;
                if (c0l + 1 > r0l + 8) s[nf][3] = -3e38f;
            }
        }

        // ---- online softmax (base-2) ----
        float mx0 = -3e38f, mx1 = -3e38f;
        #pragma unroll
        for (int nf = 0; nf < 16; nf++) {
            mx0 = fmaxf(mx0, fmaxf(s[nf][0], s[nf][1]));
            mx1 = fmaxf(mx1, fmaxf(s[nf][2], s[nf][3]));
        }
        mx0 = fmaxf(mx0, __shfl_xor_sync(0xffffffffu, mx0, 1));
        mx0 = fmaxf(mx0, __shfl_xor_sync(0xffffffffu, mx0, 2));
        mx1 = fmaxf(mx1, __shfl_xor_sync(0xffffffffu, mx1, 1));
        mx1 = fmaxf(mx1, __shfl_xor_sync(0xffffffffu, mx1, 2));
        const float m2n0 = fmaxf(m2[0], mx0 * C1);
        const float m2n1 = fmaxf(m2[1], mx1 * C1);
        const float corr0 = exp2f(m2[0] - m2n0);
        const float corr1 = exp2f(m2[1] - m2n1);
        m2[0] = m2n0; m2[1] = m2n1;

        float rs0 = 0.f, rs1 = 0.f;
        #pragma unroll
        for (int nf = 0; nf < 16; nf++) {
            s[nf][0] = exp2f(fmaf(s[nf][0], C1, -m2n0)); rs0 += s[nf][0];
            s[nf][1] = exp2f(fmaf(s[nf][1], C1, -m2n0)); rs0 += s[nf][1];
            s[nf][2] = exp2f(fmaf(s[nf][2], C1, -m2n1)); rs1 += s[nf][2];
            s[nf][3] = exp2f(fmaf(s[nf][3], C1, -m2n1)); rs1 += s[nf][3];
        }
        rs0 += __shfl_xor_sync(0xffffffffu, rs0, 1);
        rs0 += __shfl_xor_sync(0xffffffffu, rs0, 2);
        rs1 += __shfl_xor_sync(0xffffffffu, rs1, 1);
        rs1 += __shfl_xor_sync(0xffffffffu, rs1, 2);
        lsum[0] = lsum[0] * corr0 + rs0;
        lsum[1] = lsum[1] * corr1 + rs1;
        #pragma unroll
        for (int nf = 0; nf < 8; nf++) {
            o[nf][0] *= corr0; o[nf][1] *= corr0;
            o[nf][2] *= corr1; o[nf][3] *= corr1;
        }

        // ---- O += P V (P packed fp16 in-register; V via ldmatrix.trans) ----
        #pragma unroll
        for (int kc = 0; kc < 8; kc++) {
            uint32_t pa0 = pack_h(s[2 * kc][0],     s[2 * kc][1]);
            uint32_t pa1 = pack_h(s[2 * kc][2],     s[2 * kc][3]);
            uint32_t pa2 = pack_h(s[2 * kc + 1][0], s[2 * kc + 1][1]);
            uint32_t pa3 = pack_h(s[2 * kc + 1][2], s[2 * kc + 1][3]);
            const int kr = kc * 16 + vkr;
            #pragma unroll
            for (int nf2 = 0; nf2 < 4; nf2++) {
                uint32_t off = (uint32_t)(kr * 128 +
                               (((nf2 * 2 + vdc) ^ (kr & 7)) << 4));
                uint32_t v0, v1, v2, v3;
                LDSM4T(v0, v1, v2, v3, kb + A_V + off);
                MMA_F16(o[nf2 * 2],     pa0, pa1, pa2, pa3, v0, v1);
                MMA_F16(o[nf2 * 2 + 1], pa0, pa1, pa2, pa3, v2, v3);
            }
        }
    }

    // ---- normalize + write fp16 ----
    const float inv0 = 1.f / lsum[0], inv1 = 1.f / lsum[1];
    const size_t gr = (size_t)(b * SEQ + qt * 128 + w * 16 + (lane >> 2));
    const int colb = h * HD + (lane & 3) * 2;
    #pragma unroll
    for (int nf = 0; nf < 8; nf++) {
        const int col = colb + nf * 8;
        *(uint32_t*)&outa[gr * DIM + col] = pack_h(o[nf][0] * inv0, o[nf][1] * inv0);
        *(uint32_t*)&outa[(gr + 8) * DIM + col] = pack_h(o[nf][2] * inv1, o[nf][3] * inv1);
    }
}

// =============================== launch ====================================
extern "C" void kernel_launch(void* const* d_in, const int* in_sizes, int n_in,
                              void* d_out, int out_size)
{
    const float* x      = (const float*)d_in[0];
    const float* W_attn = (const float*)d_in[1];
    const float* b_attn = (const float*)d_in[2];
    const float* W_proj = (const float*)d_in[3];
    const float* b_proj = (const float*)d_in[4];
    float* out = (float*)d_out;

    __half *qkv16, *x16, *a16, *w1, *w2;
    cudaGetSymbolAddress((void**)&qkv16, g_qkv16);
    cudaGetSymbolAddress((void**)&x16, g_x16);
    cudaGetSymbolAddress((void**)&a16, g_a16);
    cudaGetSymbolAddress((void**)&w1, g_w1);
    cudaGetSymbolAddress((void**)&w2, g_w2);

    static int attrs_set = 0;
    if (!attrs_set) {
        cudaFuncSetAttribute(gemm_mma<0>, cudaFuncAttributeMaxDynamicSharedMemorySize, GEMM_SMEM);
        cudaFuncSetAttribute(gemm_mma<1>, cudaFuncAttributeMaxDynamicSharedMemorySize, GEMM_SMEM);
        cudaFuncSetAttribute(attn_mma, cudaFuncAttributeMaxDynamicSharedMemorySize, ATT_SMEM);
        attrs_set = 1;
    }

    // 1) x -> fp16
    {
        int n4 = MROWS * KTOT / 4;
        cvt_f16<<<(n4 + 255) / 256, 256>>>(x, x16, n4);
    }
    // 2) weights -> transposed fp16
    transpose_f16<<<dim3(N1 / 32, KTOT / 32), dim3(32, 8)>>>(W_attn, w1, KTOT, N1);
    transpose_f16<<<dim3(N2 / 32, KTOT / 32), dim3(32, 8)>>>(W_proj, w2, KTOT, N2);
    // 3) qkv GEMM (fp16 out)
    gemm_mma<1><<<dim3(N1 / 128, MROWS / 128), 256, GEMM_SMEM>>>(
        x16, w1, b_attn, nullptr, qkv16, N1);
    // 4) attention
    attn_mma<<<dim3(SEQ / 128, NH, BATCH), 256, ATT_SMEM>>>(qkv16, a16);
    // 5) out GEMM (fp32 out)
    gemm_mma<0><<<dim3(N2 / 128, MROWS / 128), 256, GEMM_SMEM>>>(
        a16, w2, b_proj, out, nullptr, N2);
}

// round 10
// speedup vs baseline: 2.7182x; 1.0402x over previous
#include <cuda_runtime.h>
#include <cuda_fp16.h>
#include <cstdint>
#include <cstddef>

// ---------------------------------------------------------------------------
// B=16, S=1024, DIM=768, H=12, HD=64 — fp16 tensor-core pipeline:
//   qkv(fp16) = x @ W_attn + b_attn    (fp16 MMA, fp32 accum)
//   attn      = causal MHA             (fp16 MMA, online softmax, KV-tile 64)
//   out       = attn @ W_proj + b_proj (fp16 MMA, fp32 out)
// ---------------------------------------------------------------------------
#define BATCH 16
#define SEQ   1024
#define DIM   768
#define NH    12
#define HD    64
#define MROWS (BATCH * SEQ)
#define KTOT  768
#define N1    (3 * DIM)
#define N2    DIM

__device__ __half g_qkv16[MROWS * N1];
__device__ __half g_x16[MROWS * KTOT];
__device__ __half g_a16[MROWS * KTOT];
__device__ __half g_w1[N1 * KTOT];
__device__ __half g_w2[N2 * KTOT];

// ============================ PTX helpers ==================================
__device__ __forceinline__ uint32_t smem_u32(const void* p) {
    uint32_t a;
    asm("{ .reg .u64 t; cvta.to.shared.u64 t, %1; cvt.u32.u64 %0, t; }"
        : "=r"(a) : "l"(p));
    return a;
}

#define CP16(d, s) \
    asm volatile("cp.async.cg.shared.global [%0], [%1], 16;" :: "r"(d), "l"(s))
#define CP_COMMIT() asm volatile("cp.async.commit_group;" ::: "memory")
#define CP_WAIT(n)  asm volatile("cp.async.wait_group %0;" :: "n"(n) : "memory")

#define LDSM4(r0, r1, r2, r3, a) \
    asm volatile("ldmatrix.sync.aligned.m8n8.x4.shared.b16 {%0,%1,%2,%3}, [%4];" \
                 : "=r"(r0), "=r"(r1), "=r"(r2), "=r"(r3) : "r"(a))

#define LDSM4T(r0, r1, r2, r3, a) \
    asm volatile("ldmatrix.sync.aligned.m8n8.x4.trans.shared.b16 {%0,%1,%2,%3}, [%4];" \
                 : "=r"(r0), "=r"(r1), "=r"(r2), "=r"(r3) : "r"(a))

#define MMA_F16(d, a0, a1, a2, a3, b0, b1) \
    asm volatile("mma.sync.aligned.m16n8k16.row.col.f32.f16.f16.f32 " \
                 "{%0,%1,%2,%3}, {%4,%5,%6,%7}, {%8,%9}, {%0,%1,%2,%3};" \
                 : "+f"((d)[0]), "+f"((d)[1]), "+f"((d)[2]), "+f"((d)[3]) \
                 : "r"(a0), "r"(a1), "r"(a2), "r"(a3), "r"(b0), "r"(b1))

__device__ __forceinline__ uint32_t pack_h(float x, float y) {
    __half2 t = __float22half2_rn(make_float2(x, y));
    return *(uint32_t*)&t;
}

// ======================= conversion kernels ================================
__global__ __launch_bounds__(256) void cvt_f16(
    const float* __restrict__ in, __half* __restrict__ out, int n4)
{
    int i = blockIdx.x * 256 + threadIdx.x;
    if (i >= n4) return;
    float4 v = ((const float4*)in)[i];
    ((uint32_t*)out)[i * 2 + 0] = pack_h(v.x, v.y);
    ((uint32_t*)out)[i * 2 + 1] = pack_h(v.z, v.w);
}

__global__ __launch_bounds__(256) void transpose_f16(
    const float* __restrict__ W, __half* __restrict__ T, int K, int N)
{
    __shared__ float tile[32][33];
    int tx = threadIdx.x, ty = threadIdx.y;
    int nx = blockIdx.x * 32 + tx;
    int ky = blockIdx.y * 32 + ty;
    #pragma unroll
    for (int j = 0; j < 32; j += 8)
        tile[ty + j][tx] = W[(size_t)(ky + j) * N + nx];
    __syncthreads();
    int kx = blockIdx.y * 32 + tx;
    int ny = blockIdx.x * 32 + ty;
    #pragma unroll
    for (int j = 0; j < 32; j += 8)
        T[(size_t)(ny + j) * K + kx] = __float2half(tile[tx][ty + j]);
}

// ================== HMMA GEMM (single-term fp16) ===========================
// 128x128 tile, BK=64, 3 stages x 32KB, 256 threads, 2 CTAs/SM.
// Pipeline per iter: WAIT -> sync -> issue load(i+2) -> compute(i).
#define NSTG    3
#define NIT     12
#define T_A     0
#define T_B     16384
#define STG     32768
#define GEMM_SMEM (NSTG * STG)     // 98304

__device__ __forceinline__ void stage_load(
    uint32_t sstage, const __half* A, const __half* B,
    int mtile, int ntile, int kiter, int tid)
{
    #pragma unroll
    for (int j = 0; j < 4; j++) {
        int idx = tid + j * 256;
        int r = idx >> 3, c = idx & 7;
        uint32_t so = (uint32_t)(r * 128 + ((c ^ (r & 7)) << 4));
        CP16(sstage + T_A + so,
             (const char*)(A + (size_t)(mtile * 128 + r) * KTOT + kiter * 64 + c * 8));
        CP16(sstage + T_B + so,
             (const char*)(B + (size_t)(ntile * 128 + r) * KTOT + kiter * 64 + c * 8));
    }
}

template<int OUT16>
__global__ __launch_bounds__(256, 2) void gemm_mma(
    const __half* __restrict__ A, const __half* __restrict__ B,
    const float* __restrict__ bias, float* __restrict__ Cf,
    __half* __restrict__ Ch, int Ntot)
{
    extern __shared__ char smem[];
    const uint32_t sb = smem_u32(smem);
    const int tid = threadIdx.x, lane = tid & 31, wid = tid >> 5;
    const int mtile = blockIdx.y, ntile = blockIdx.x;
    const int wm = (wid & 3) * 32;
    const int wn = (wid >> 2) * 64;

    const int rowA  = wm + (lane & 15);
    const int xorA  = rowA & 7;
    const int clA   = lane >> 4;
    const int rowB  = wn + ((lane >> 4) << 3) + (lane & 7);
    const int xorB  = rowB & 7;
    const int clB   = (lane >> 3) & 1;

    float acc[2][8][4];
    #pragma unroll
    for (int mf = 0; mf < 2; mf++)
        #pragma unroll
        for (int nf = 0; nf < 8; nf++)
            #pragma unroll
            for (int q = 0; q < 4; q++) acc[mf][nf][q] = 0.f;

    stage_load(sb + 0 * STG, A, B, mtile, ntile, 0, tid); CP_COMMIT();
    stage_load(sb + 1 * STG, A, B, mtile, ntile, 1, tid); CP_COMMIT();

    for (int i = 0; i < NIT; i++) {
        // Retire the group for stage i (pending: {i, i+1}); tail iters drain all.
        if (i + 1 < NIT) { CP_WAIT(1); } else { CP_WAIT(0); }
        __syncthreads();   // publish stage i data; all reads of stage (i+2)%3 done

        if (i + 2 < NIT) {
            stage_load(sb + ((i + 2) % NSTG) * STG, A, B, mtile, ntile, i + 2, tid);
            CP_COMMIT();
        }

        const uint32_t st = sb + (i % NSTG) * STG;
        #pragma unroll
        for (int ks = 0; ks < 4; ks++) {
            uint32_t ar[2][4], br[8][2];
            #pragma unroll
            for (int mf = 0; mf < 2; mf++) {
                uint32_t off = (uint32_t)((rowA + mf * 16) * 128 +
                               ((((ks << 1) + clA) ^ xorA) << 4));
                LDSM4(ar[mf][0], ar[mf][1], ar[mf][2], ar[mf][3], st + T_A + off);
            }
            #pragma unroll
            for (int nf2 = 0; nf2 < 4; nf2++) {
                uint32_t off = (uint32_t)((rowB + nf2 * 16) * 128 +
                               ((((ks << 1) + clB) ^ xorB) << 4));
                LDSM4(br[nf2 * 2][0], br[nf2 * 2][1],
                      br[nf2 * 2 + 1][0], br[nf2 * 2 + 1][1], st + T_B + off);
            }
            #pragma unroll
            for (int mf = 0; mf < 2; mf++)
                #pragma unroll
                for (int nf = 0; nf < 8; nf++)
                    MMA_F16(acc[mf][nf], ar[mf][0], ar[mf][1], ar[mf][2], ar[mf][3],
                            br[nf][0], br[nf][1]);
        }
    }

    #pragma unroll
    for (int mf = 0; mf < 2; mf++) {
        #pragma unroll
        for (int nf = 0; nf < 8; nf++) {
            const int col = ntile * 128 + wn + nf * 8 + (lane & 3) * 2;
            const int row0 = mtile * 128 + wm + mf * 16 + (lane >> 2);
            const float b0 = bias[col], b1 = bias[col + 1];
            float v0 = acc[mf][nf][0] + b0, v1 = acc[mf][nf][1] + b1;
            float v2 = acc[mf][nf][2] + b0, v3 = acc[mf][nf][3] + b1;
            if (OUT16) {
                *(uint32_t*)&Ch[(size_t)row0 * Ntot + col] = pack_h(v0, v1);
                *(uint32_t*)&Ch[(size_t)(row0 + 8) * Ntot + col] = pack_h(v2, v3);
            } else {
                *(float2*)&Cf[(size_t)row0 * Ntot + col] = make_float2(v0, v1);
                *(float2*)&Cf[(size_t)(row0 + 8) * Ntot + col] = make_float2(v2, v3);
            }
        }
    }
}

// ============== tensor-core causal flash attention (fp16) ==================
// CTA: 128 q-rows x 1 head, 8 warps, KV-tile 64 rows.
// smem: Q 16KB + 2 x (K 8KB + V 8KB) = 48KB -> 2 CTAs/SM.
#define AQ_OFF   0
#define ABUF0    16384
#define A_V      8192             // V offset within a buffer
#define A_BUF    16384
#define ATT_SMEM 49152
#define C1 0.18033688011112042f   // 0.125 * log2(e)

__device__ __forceinline__ void attn_load_kv(
    uint32_t bufbase, const __half* qkv, int b, int h, int jt, int tid)
{
    #pragma unroll
    for (int j = 0; j < 4; j++) {
        int idx = tid + j * 256;
        if (idx < 512) {
            int r = idx >> 3, c = idx & 7;
            const __half* src = qkv
                + (size_t)(b * SEQ + jt * 64 + r) * N1 + DIM + h * HD + c * 8;
            CP16(bufbase + r * 128 + ((c ^ (r & 7)) << 4), src);
        } else {
            int rem = idx - 512;
            int r = rem >> 3, c = rem & 7;
            const __half* src = qkv
                + (size_t)(b * SEQ + jt * 64 + r) * N1 + 2 * DIM + h * HD + c * 8;
            CP16(bufbase + A_V + r * 128 + ((c ^ (r & 7)) << 4), src);
        }
    }
}

__global__ __launch_bounds__(256, 2) void attn_mma(
    const __half* __restrict__ qkv, __half* __restrict__ outa)
{
    extern __shared__ char smem[];
    const uint32_t sb = smem_u32(smem);
    const int tid = threadIdx.x, lane = tid & 31, w = tid >> 5;
    const int qt = gridDim.x - 1 - blockIdx.x;   // longest-first
    const int h = blockIdx.y, b = blockIdx.z;
    const int nt = 2 * qt + 2;                    // KV tiles of 64

    // ---- stage Q tile (128 x 64), then to fragments ----
    #pragma unroll
    for (int j = 0; j < 4; j++) {
        int idx = tid + j * 256;
        int r = idx >> 3, c = idx & 7;
        const __half* src = qkv
            + (size_t)(b * SEQ + qt * 128 + r) * N1 + h * HD + c * 8;
        CP16(sb + AQ_OFF + r * 128 + ((c ^ (r & 7)) << 4), src);
    }
    CP_COMMIT(); CP_WAIT(0);
    __syncthreads();

    const int rowA = w * 16 + (lane & 15);
    const int clA = lane >> 4, xorA = rowA & 7;
    uint32_t qf[4][4];
    #pragma unroll
    for (int ks = 0; ks < 4; ks++) {
        uint32_t off = (uint32_t)(rowA * 128 + ((((ks << 1) + clA) ^ xorA) << 4));
        LDSM4(qf[ks][0], qf[ks][1], qf[ks][2], qf[ks][3], sb + AQ_OFF + off);
    }

    attn_load_kv(sb + ABUF0, qkv, b, h, 0, tid);
    CP_COMMIT();

    float m2[2] = {-1e30f, -1e30f}, lsum[2] = {0.f, 0.f};
    float o[8][4];
    #pragma unroll
    for (int nf = 0; nf < 8; nf++)
        #pragma unroll
        for (int q = 0; q < 4; q++) o[nf][q] = 0.f;

    const int rowB = ((lane >> 4) << 3) + (lane & 7);
    const int clB = (lane >> 3) & 1, xorB = lane & 7;
    const int vkr = (lane & 7) + ((lane >> 3) & 1) * 8;
    const int vdc = lane >> 4;
    const int r0g = qt * 128 + w * 16 + (lane >> 2);   // global q row (first half)

    for (int jt = 0; jt < nt; jt++) {
        CP_WAIT(0);
        __syncthreads();
        if (jt + 1 < nt) {
            attn_load_kv(sb + ABUF0 + ((jt + 1) & 1) * A_BUF, qkv, b, h, jt + 1, tid);
            CP_COMMIT();
        }
        const uint32_t kb = sb + ABUF0 + (jt & 1) * A_BUF;

        // ---- scores S = Q K^T  (16 q-rows x 64 kv per warp) ----
        float s[8][4];
        #pragma unroll
        for (int nf = 0; nf < 8; nf++)
            #pragma unroll
            for (int q = 0; q < 4; q++) s[nf][q] = 0.f;

        #pragma unroll
        for (int ks = 0; ks < 4; ks++) {
            #pragma unroll
            for (int nf2 = 0; nf2 < 4; nf2++) {
                uint32_t off = (uint32_t)((rowB + nf2 * 16) * 128 +
                               ((((ks << 1) + clB) ^ xorB) << 4));
                uint32_t k0, k1, k2, k3;
                LDSM4(k0, k1, k2, k3, kb + off);
                MMA_F16(s[nf2 * 2],     qf[ks][0], qf[ks][1], qf[ks][2], qf[ks][3], k0, k1);
                MMA_F16(s[nf2 * 2 + 1], qf[ks][0], qf[ks][1], qf[ks][2], qf[ks][3], k2, k3);
            }
        }

        // ---- causal mask (tiles overlapping the diagonal) ----
        if (jt >= 2 * qt) {
            #pragma unroll
            for (int nf = 0; nf < 8; nf++) {
                const int c0g = jt * 64 + nf * 8 + (lane & 3) * 2;
                if (c0g     > r0g)     s[nf][0] = -3e38f;
                if (c0g + 1 > r0g)     s[nf][1] = -3e38f;
                if (c0g     > r0g + 8) s[nf][2] = -3e38f;
                if (c0g + 1 > r0g + 8) s[nf][3] = -3e38f;
            }
        }

        // ---- online softmax (base-2) ----
        float mx0 = -3e38f, mx1 = -3e38f;
        #pragma unroll
        for (int nf = 0; nf < 8; nf++) {
            mx0 = fmaxf(mx0, fmaxf(s[nf][0], s[nf][1]));
            mx1 = fmaxf(mx1, fmaxf(s[nf][2], s[nf][3]));
        }
        mx0 = fmaxf(mx0, __shfl_xor_sync(0xffffffffu, mx0, 1));
        mx0 = fmaxf(mx0, __shfl_xor_sync(0xffffffffu, mx0, 2));
        mx1 = fmaxf(mx1, __shfl_xor_sync(0xffffffffu, mx1, 1));
        mx1 = fmaxf(mx1, __shfl_xor_sync(0xffffffffu, mx1, 2));
        const float m2n0 = fmaxf(m2[0], mx0 * C1);
        const float m2n1 = fmaxf(m2[1], mx1 * C1);
        const float corr0 = exp2f(m2[0] - m2n0);
        const float corr1 = exp2f(m2[1] - m2n1);
        m2[0] = m2n0; m2[1] = m2n1;

        float rs0 = 0.f, rs1 = 0.f;
        #pragma unroll
        for (int nf = 0; nf < 8; nf++) {
            s[nf][0] = exp2f(fmaf(s[nf][0], C1, -m2n0)); rs0 += s[nf][0];
            s[nf][1] = exp2f(fmaf(s[nf][1], C1, -m2n0)); rs0 += s[nf][1];
            s[nf][2] = exp2f(fmaf(s[nf][2], C1, -m2n1)); rs1 += s[nf][2];
            s[nf][3] = exp2f(fmaf(s[nf][3], C1, -m2n1)); rs1 += s[nf][3];
        }
        rs0 += __shfl_xor_sync(0xffffffffu, rs0, 1);
        rs0 += __shfl_xor_sync(0xffffffffu, rs0, 2);
        rs1 += __shfl_xor_sync(0xffffffffu, rs1, 1);
        rs1 += __shfl_xor_sync(0xffffffffu, rs1, 2);
        lsum[0] = lsum[0] * corr0 + rs0;
        lsum[1] = lsum[1] * corr1 + rs1;
        #pragma unroll
        for (int nf = 0; nf < 8; nf++) {
            o[nf][0] *= corr0; o[nf][1] *= corr0;
            o[nf][2] *= corr1; o[nf][3] *= corr1;
        }

        // ---- O += P V (P packed fp16 in-register; V via ldmatrix.trans) ----
        #pragma unroll
        for (int kc = 0; kc < 4; kc++) {
            uint32_t pa0 = pack_h(s[2 * kc][0],     s[2 * kc][1]);
            uint32_t pa1 = pack_h(s[2 * kc][2],     s[2 * kc][3]);
            uint32_t pa2 = pack_h(s[2 * kc + 1][0], s[2 * kc + 1][1]);
            uint32_t pa3 = pack_h(s[2 * kc + 1][2], s[2 * kc + 1][3]);
            const int kr = kc * 16 + vkr;
            #pragma unroll
            for (int nf2 = 0; nf2 < 4; nf2++) {
                uint32_t off = (uint32_t)(kr * 128 +
                               (((nf2 * 2 + vdc) ^ (kr & 7)) << 4));
                uint32_t v0, v1, v2, v3;
                LDSM4T(v0, v1, v2, v3, kb + A_V + off);
                MMA_F16(o[nf2 * 2],     pa0, pa1, pa2, pa3, v0, v1);
                MMA_F16(o[nf2 * 2 + 1], pa0, pa1, pa2, pa3, v2, v3);
            }
        }
    }

    // ---- normalize + write fp16 ----
    const float inv0 = 1.f / lsum[0], inv1 = 1.f / lsum[1];
    const size_t gr = (size_t)(b * SEQ + qt * 128 + w * 16 + (lane >> 2));
    const int colb = h * HD + (lane & 3) * 2;
    #pragma unroll
    for (int nf = 0; nf < 8; nf++) {
        const int col = colb + nf * 8;
        *(uint32_t*)&outa[gr * DIM + col] = pack_h(o[nf][0] * inv0, o[nf][1] * inv0);
        *(uint32_t*)&outa[(gr + 8) * DIM + col] = pack_h(o[nf][2] * inv1, o[nf][3] * inv1);
    }
}

// =============================== launch ====================================
extern "C" void kernel_launch(void* const* d_in, const int* in_sizes, int n_in,
                              void* d_out, int out_size)
{
    const float* x      = (const float*)d_in[0];
    const float* W_attn = (const float*)d_in[1];
    const float* b_attn = (const float*)d_in[2];
    const float* W_proj = (const float*)d_in[3];
    const float* b_proj = (const float*)d_in[4];
    float* out = (float*)d_out;

    __half *qkv16, *x16, *a16, *w1, *w2;
    cudaGetSymbolAddress((void**)&qkv16, g_qkv16);
    cudaGetSymbolAddress((void**)&x16, g_x16);
    cudaGetSymbolAddress((void**)&a16, g_a16);
    cudaGetSymbolAddress((void**)&w1, g_w1);
    cudaGetSymbolAddress((void**)&w2, g_w2);

    static int attrs_set = 0;
    if (!attrs_set) {
        cudaFuncSetAttribute(gemm_mma<0>, cudaFuncAttributeMaxDynamicSharedMemorySize, GEMM_SMEM);
        cudaFuncSetAttribute(gemm_mma<1>, cudaFuncAttributeMaxDynamicSharedMemorySize, GEMM_SMEM);
        cudaFuncSetAttribute(attn_mma, cudaFuncAttributeMaxDynamicSharedMemorySize, ATT_SMEM);
        attrs_set = 1;
    }

    // 1) x -> fp16
    {
        int n4 = MROWS * KTOT / 4;
        cvt_f16<<<(n4 + 255) / 256, 256>>>(x, x16, n4);
    }
    // 2) weights -> transposed fp16
    transpose_f16<<<dim3(N1 / 32, KTOT / 32), dim3(32, 8)>>>(W_attn, w1, KTOT, N1);
    transpose_f16<<<dim3(N2 / 32, KTOT / 32), dim3(32, 8)>>>(W_proj, w2, KTOT, N2);
    // 3) qkv GEMM (fp16 out)
    gemm_mma<1><<<dim3(N1 / 128, MROWS / 128), 256, GEMM_SMEM>>>(
        x16, w1, b_attn, nullptr, qkv16, N1);
    // 4) attention
    attn_mma<<<dim3(SEQ / 128, NH, BATCH), 256, ATT_SMEM>>>(qkv16, a16);
    // 5) out GEMM (fp32 out)
    gemm_mma<0><<<dim3(N2 / 128, MROWS / 128), 256, GEMM_SMEM>>>(
        a16, w2, b_proj, out, nullptr, N2);
}